// round 13
// baseline (speedup 1.0000x reference)
#include <cuda_runtime.h>
#include <cuda_bf16.h>
#include <math.h>
#include <stdint.h>

static constexpr int VOCAB = 267735;
static constexpr int ROWS  = 512;

// bf16 scratch element offsets (convert region, then packed Y)
static constexpr size_t B_W0 = 0;
static constexpr size_t B_W1 = 20480000;
static constexpr size_t B_W2 = 25600000;
static constexpr size_t B_W3 = 35840000;
static constexpr size_t B_P0 = 36923760;   // packed projections (1360 rows x 1024)
static constexpr size_t B_H  = 38316400;
static constexpr size_t B_CONV_END = 38840688;
static constexpr size_t B_Y  = 38840688;   // packed Y [512 x 1360]
static constexpr size_t B_END = 38840688 + 512 * 1360;

__device__ __align__(16) __nv_bfloat16 g_bf[B_END];
__device__ __align__(16) float g_f32[ROWS * 3 + ROWS * 4];   // clog[512*3], lse[512*4]
__device__ __align__(16) float g_sum[ROWS * 4];              // per-(row,cluster) exp sums

// ---------------- fast exp (FMA-only, |x| < ~20, no clamp) ----------------
__device__ __forceinline__ float fast_exp(float x) {
    float y = x * 1.4426950408889634f;
    float t = y + 12582912.0f;                       // magic round-to-nearest
    int   n = __float_as_int(t) - 0x4B400000;
    float f = y - (t - 12582912.0f);                 // f in [-0.5, 0.5]
    float u = f * 0.6931471805599453f;               // |u| <= 0.347
    float p = 1.0f + u*(1.0f + u*(0.5f + u*(0.16666667f + u*0.041666667f)));
    return p * __int_as_float((n + 127) << 23);
}

// ---------------- zero the sums ----------------
__global__ void zero_k(float* __restrict__ gsum) {
    int i = blockIdx.x * blockDim.x + threadIdx.x;
    if (i < ROWS * 4) gsum[i] = 0.0f;
}

// ---------------- fused fp32 -> bf16 convert ----------------
__global__ void conv_all_k(const float* __restrict__ w0, const float* __restrict__ w1,
                           const float* __restrict__ w2, const float* __restrict__ w3,
                           const float* __restrict__ p0, const float* __restrict__ p1,
                           const float* __restrict__ p2, const float* __restrict__ p3,
                           const float* __restrict__ hh)
{
    const size_t e1 = 20480000, e2 = 25600000, e3 = 35840000, e4 = 36923760;
    const size_t e5 = 37972336, e6 = 38234480, e7 = 38300016, e8 = 38316400;
    const size_t nchunks = B_CONV_END / 8;
    size_t stride = (size_t)gridDim.x * blockDim.x;
    for (size_t c = (size_t)blockIdx.x * blockDim.x + threadIdx.x; c < nchunks; c += stride) {
        size_t e = c * 8;
        const float* src;
        size_t base;
        if      (e < e1) { src = w0; base = 0;  }
        else if (e < e2) { src = w1; base = e1; }
        else if (e < e3) { src = w2; base = e2; }
        else if (e < e4) { src = w3; base = e3; }
        else if (e < e5) { src = p0; base = e4; }
        else if (e < e6) { src = p1; base = e5; }
        else if (e < e7) { src = p2; base = e6; }
        else if (e < e8) { src = p3; base = e7; }
        else             { src = hh; base = e8; }
        const float4* s = reinterpret_cast<const float4*>(src + (e - base));
        float4 v0 = s[0];
        float4 v1 = s[1];
        __nv_bfloat162 a0 = __floats2bfloat162_rn(v0.x, v0.y);
        __nv_bfloat162 a1 = __floats2bfloat162_rn(v0.z, v0.w);
        __nv_bfloat162 a2 = __floats2bfloat162_rn(v1.x, v1.y);
        __nv_bfloat162 a3 = __floats2bfloat162_rn(v1.z, v1.w);
        uint4 u;
        u.x = *reinterpret_cast<uint32_t*>(&a0);
        u.y = *reinterpret_cast<uint32_t*>(&a1);
        u.z = *reinterpret_cast<uint32_t*>(&a2);
        u.w = *reinterpret_cast<uint32_t*>(&a3);
        *reinterpret_cast<uint4*>(g_bf + e) = u;
    }
}

// ---------------- common PTX helpers ----------------
__device__ __forceinline__ uint32_t smem_u32(const void* p) {
    uint32_t a;
    asm("{ .reg .u64 t; cvta.to.shared.u64 t, %1; cvt.u32.u64 %0, t; }" : "=r"(a) : "l"(p));
    return a;
}
__device__ __forceinline__ void mma16816(float* c, const uint32_t* a, const uint32_t* b) {
    asm volatile(
        "mma.sync.aligned.m16n8k16.row.col.f32.bf16.bf16.f32 "
        "{%0,%1,%2,%3}, {%4,%5,%6,%7}, {%8,%9}, {%0,%1,%2,%3};"
        : "+f"(c[0]), "+f"(c[1]), "+f"(c[2]), "+f"(c[3])
        : "r"(a[0]), "r"(a[1]), "r"(a[2]), "r"(a[3]), "r"(b[0]), "r"(b[1]));
}
__device__ __forceinline__ void ldsm_x4(uint32_t& r0, uint32_t& r1, uint32_t& r2, uint32_t& r3,
                                        uint32_t addr) {
    asm volatile("ldmatrix.sync.aligned.m8n8.x4.shared.b16 {%0,%1,%2,%3}, [%4];"
        : "=r"(r0), "=r"(r1), "=r"(r2), "=r"(r3) : "r"(addr));
}
__device__ __forceinline__ void cp16(uint32_t dst, const void* src, bool valid) {
    int sz = valid ? 16 : 0;
    asm volatile("cp.async.cg.shared.global [%0], [%1], 16, %2;"
        :: "r"(dst), "l"(src), "r"(sz) : "memory");
}
__device__ __forceinline__ void cp_commit() {
    asm volatile("cp.async.commit_group;" ::: "memory");
}
__device__ __forceinline__ void cp_wait0() {
    asm volatile("cp.async.wait_group 0;" ::: "memory");
}

// ================= fused logit GEMM =================
// CTA tile 128x64, 256 threads, 8 warps as 4M x 2N (warp tile 32x32), 3 CTAs/SM.
// mode 0 (grid.x = 4185, all clusters): GEMM; store RAW logits for clusters 0/1;
//        accumulate plain exp-sums for all clusters via atomicAdd.
// mode 1 (grid.x = 3559, clusters 2/3): GEMM recompute; store adjusted log-probs.
static constexpr int A_BUF  = 128 * 144;               // 18432 bytes
static constexpr int BB_BUF = 64 * 144;                // 9216 bytes
static constexpr int SM_LOG = 2 * A_BUF + 2 * BB_BUF;  // 55296

__global__ void __launch_bounds__(256, 3)
logits_k(int mode,
         float* __restrict__ out,
         const float* __restrict__ bias0, const float* __restrict__ bias1,
         const float* __restrict__ bias2, const float* __restrict__ bias3,
         float* __restrict__ gsum,
         const float* __restrict__ clog,
         const float* __restrict__ lse)
{
    // cluster tables in 64-col tile space: {313, 313, 2500, 1059}
    const int    ct_base[5] = {0, 313, 626, 3126, 4185};
    const int    ct_k[4]    = {1024, 256, 64, 16};
    const int    ct_aoff[4] = {0, 1024, 1280, 1344};
    const size_t ct_boff[4] = {B_W0, B_W1, B_W2, B_W3};
    const int    ct_n[4]    = {20000, 20000, 160000, 67735};
    const int    ct_col[4]  = {0, 20000, 40000, 200000};

    extern __shared__ __align__(16) char smem[];
    const uint32_t sb = smem_u32(smem);

    const int t = blockIdx.x + ((mode == 1) ? 626 : 0);
    int c;
    if      (t < ct_base[1]) c = 0;
    else if (t < ct_base[2]) c = 1;
    else if (t < ct_base[3]) c = 2;
    else                     c = 3;
    const int tl = t - ct_base[c];
    const int n0 = tl * 64;
    const int K  = ct_k[c];
    const int N  = ct_n[c];
    const int mt = blockIdx.y;
    const bool full = (n0 + 64 <= N);
    const __nv_bfloat16* A = g_bf + B_Y + ct_aoff[c];
    const __nv_bfloat16* B = g_bf + ct_boff[c];
    const float* bias = (c == 0) ? bias0 : (c == 1) ? bias1 : (c == 2) ? bias2 : bias3;

    const int tid  = threadIdx.x;
    const int wid  = tid >> 5, lane = tid & 31;
    const int wm   = wid & 3;          // 4 M sub-tiles of 32 rows
    const int wn   = wid >> 2;         // 2 N sub-tiles of 32 cols
    const int g    = lane >> 2;
    const int tg   = lane & 3;

    float acc[2][4][4];
    #pragma unroll
    for (int mi = 0; mi < 2; mi++)
        #pragma unroll
        for (int ni = 0; ni < 4; ni++)
            #pragma unroll
            for (int q = 0; q < 4; q++) acc[mi][ni][q] = 0.0f;

    const int lrow = tid >> 1;           // A: 0..127
    const int lseg = (tid & 1) * 4;      // A: 0 or 4
    const int brow = tid >> 2;           // B: 0..63
    const int bseg = (tid & 3) * 2;      // B: 0,2,4,6
    const int nkc = (K + 63) >> 6;

    // prologue
    {
        #pragma unroll
        for (int i = 0; i < 4; i++) {
            int kk = (lseg + i) * 8;
            cp16(sb + lrow * 144 + (lseg + i) * 16,
                 A + (size_t)(mt * 128 + lrow) * 1360 + kk, kk < K);
        }
        int gn = n0 + brow;
        #pragma unroll
        for (int i = 0; i < 2; i++) {
            int kk = (bseg + i) * 8;
            cp16(sb + 2 * A_BUF + brow * 144 + (bseg + i) * 16,
                 B + (size_t)(gn < N ? gn : 0) * K + kk, gn < N && kk < K);
        }
        cp_commit();
    }

    for (int kc = 0; kc < nkc; kc++) {
        const int p = kc & 1;
        cp_wait0();
        __syncthreads();

        if (kc + 1 < nkc) {
            const int k0 = (kc + 1) << 6;
            const int q = p ^ 1;
            #pragma unroll
            for (int i = 0; i < 4; i++) {
                int kk = k0 + (lseg + i) * 8;
                cp16(sb + q * A_BUF + lrow * 144 + (lseg + i) * 16,
                     A + (size_t)(mt * 128 + lrow) * 1360 + kk, kk < K);
            }
            int gn = n0 + brow;
            #pragma unroll
            for (int i = 0; i < 2; i++) {
                int kk = k0 + (bseg + i) * 8;
                cp16(sb + 2 * A_BUF + q * BB_BUF + brow * 144 + (bseg + i) * 16,
                     B + (size_t)(gn < N ? gn : 0) * K + kk, gn < N && kk < K);
            }
            cp_commit();
        }

        const uint32_t abase = sb + p * A_BUF;
        const uint32_t bbase = sb + 2 * A_BUF + p * BB_BUF;

        #pragma unroll
        for (int ks = 0; ks < 4; ks++) {
            const int kb = ks * 16;
            uint32_t afrag[2][4];
            #pragma unroll
            for (int mi = 0; mi < 2; mi++) {
                int row = wm * 32 + mi * 16 + (lane & 15);
                int col = kb + (lane >> 4) * 8;
                ldsm_x4(afrag[mi][0], afrag[mi][1], afrag[mi][2], afrag[mi][3],
                        abase + row * 144 + col * 2);
            }
            #pragma unroll
            for (int nj = 0; nj < 2; nj++) {
                int row = wn * 32 + nj * 16 + ((lane >> 4) << 3) + (lane & 7);
                int col = kb + ((lane >> 3) & 1) * 8;
                uint32_t b0, b1, b2, b3;
                ldsm_x4(b0, b1, b2, b3, bbase + row * 144 + col * 2);
                uint32_t be[2] = {b0, b1};
                uint32_t bo[2] = {b2, b3};
                #pragma unroll
                for (int mi = 0; mi < 2; mi++) {
                    mma16816(acc[mi][2 * nj],     afrag[mi], be);
                    mma16816(acc[mi][2 * nj + 1], afrag[mi], bo);
                }
            }
        }
        __syncthreads();
    }

    // bias fold (guard-free when tile is interior)
    if (full) {
        #pragma unroll
        for (int ni = 0; ni < 4; ni++) {
            #pragma unroll
            for (int q = 0; q < 2; q++) {
                int col = n0 + wn * 32 + ni * 8 + tg * 2 + q;
                float bvq = bias[col];
                #pragma unroll
                for (int mi = 0; mi < 2; mi++) {
                    acc[mi][ni][q]     += bvq;
                    acc[mi][ni][q + 2] += bvq;
                }
            }
        }
    } else {
        #pragma unroll
        for (int ni = 0; ni < 4; ni++) {
            #pragma unroll
            for (int q = 0; q < 2; q++) {
                int col = n0 + wn * 32 + ni * 8 + tg * 2 + q;
                float bvq = (col < N) ? bias[col] : 0.0f;
                #pragma unroll
                for (int mi = 0; mi < 2; mi++) {
                    acc[mi][ni][q]     += bvq;
                    acc[mi][ni][q + 2] += bvq;
                }
            }
        }
    }

    float* stage = reinterpret_cast<float*>(smem);                 // [128][68]
    float* saux  = reinterpret_cast<float*>(smem) + 128 * 68;      // [256]

    if (mode == 0) {
        // ---- plain exp sums (no max shift: |logit| < ~3) ----
        #pragma unroll
        for (int mi = 0; mi < 2; mi++) {
            int rl = wm * 32 + mi * 16 + g;
            float s_lo = 0.0f, s_hi = 0.0f;
            if (full) {
                #pragma unroll
                for (int ni = 0; ni < 4; ni++) {
                    s_lo += fast_exp(acc[mi][ni][0]);
                    s_hi += fast_exp(acc[mi][ni][2]);
                    s_lo += fast_exp(acc[mi][ni][1]);
                    s_hi += fast_exp(acc[mi][ni][3]);
                }
            } else {
                #pragma unroll
                for (int ni = 0; ni < 4; ni++) {
                    int col = n0 + wn * 32 + ni * 8 + tg * 2;
                    if (col < N) {
                        s_lo += fast_exp(acc[mi][ni][0]);
                        s_hi += fast_exp(acc[mi][ni][2]);
                    }
                    if (col + 1 < N) {
                        s_lo += fast_exp(acc[mi][ni][1]);
                        s_hi += fast_exp(acc[mi][ni][3]);
                    }
                }
            }
            s_lo += __shfl_xor_sync(0xffffffff, s_lo, 1);
            s_lo += __shfl_xor_sync(0xffffffff, s_lo, 2);
            s_hi += __shfl_xor_sync(0xffffffff, s_hi, 1);
            s_hi += __shfl_xor_sync(0xffffffff, s_hi, 2);
            if (tg == 0) {
                saux[rl * 2 + wn] = s_lo;
                saux[(rl + 8) * 2 + wn] = s_hi;
            }
        }
        if (c < 2) {
            #pragma unroll
            for (int mi = 0; mi < 2; mi++) {
                int rl = wm * 32 + mi * 16 + g;
                #pragma unroll
                for (int ni = 0; ni < 4; ni++) {
                    int cl = wn * 32 + ni * 8 + tg * 2;
                    stage[rl * 68 + cl]           = acc[mi][ni][0];
                    stage[rl * 68 + cl + 1]       = acc[mi][ni][1];
                    stage[(rl + 8) * 68 + cl]     = acc[mi][ni][2];
                    stage[(rl + 8) * 68 + cl + 1] = acc[mi][ni][3];
                }
            }
        }
        __syncthreads();
        if (tid < 128) {
            float s = saux[tid * 2] + saux[tid * 2 + 1];
            atomicAdd(&gsum[(mt * 128 + tid) * 4 + c], s);
        }
        if (c < 2) {
            if (full) {
                #pragma unroll 4
                for (int it = 0; it < 32; it++) {
                    int row = (it & 15) * 8 + wid;
                    int col = (it >> 4) * 32 + lane;
                    out[(size_t)(mt * 128 + row) * VOCAB + ct_col[c] + n0 + col] =
                        stage[row * 68 + col];
                }
            } else {
                #pragma unroll 4
                for (int it = 0; it < 32; it++) {
                    int row = (it & 15) * 8 + wid;
                    int col = (it >> 4) * 32 + lane;
                    int gcol = n0 + col;
                    if (gcol < N)
                        out[(size_t)(mt * 128 + row) * VOCAB + ct_col[c] + gcol] =
                            stage[row * 68 + col];
                }
            }
        }
    } else {
        // ---- pass 2 (clusters 2/3): adjusted log-prob store ----
        if (tid < 128) {
            int grow = mt * 128 + tid;
            float l0 = lse[grow * 4 + 0];
            saux[tid] = clog[grow * 3 + (c - 1)] - l0 - lse[grow * 4 + c];
        }
        #pragma unroll
        for (int mi = 0; mi < 2; mi++) {
            int rl = wm * 32 + mi * 16 + g;
            #pragma unroll
            for (int ni = 0; ni < 4; ni++) {
                int cl = wn * 32 + ni * 8 + tg * 2;
                stage[rl * 68 + cl]           = acc[mi][ni][0];
                stage[rl * 68 + cl + 1]       = acc[mi][ni][1];
                stage[(rl + 8) * 68 + cl]     = acc[mi][ni][2];
                stage[(rl + 8) * 68 + cl + 1] = acc[mi][ni][3];
            }
        }
        __syncthreads();
        if (full) {
            #pragma unroll 4
            for (int it = 0; it < 32; it++) {
                int row = (it & 15) * 8 + wid;
                int col = (it >> 4) * 32 + lane;
                float v = stage[row * 68 + col] + saux[row];
                out[(size_t)(mt * 128 + row) * VOCAB + ct_col[c] + n0 + col] = v;
            }
        } else {
            #pragma unroll 4
            for (int it = 0; it < 32; it++) {
                int row = (it & 15) * 8 + wid;
                int col = (it >> 4) * 32 + lane;
                int gcol = n0 + col;
                if (gcol < N) {
                    float v = stage[row * 68 + col] + saux[row];
                    out[(size_t)(mt * 128 + row) * VOCAB + ct_col[c] + gcol] = v;
                }
            }
        }
    }
}

// ================= projection GEMM (bf16 out), 128x256 tile, 8 warps 2Mx4N =================
static constexpr int A_BUF_B = 128 * 144;
static constexpr int B_BUF_B = 256 * 144;
static constexpr int SM_GEMM = 2 * A_BUF_B + 2 * B_BUF_B;

__global__ void __launch_bounds__(256)
proj_gemm_k(const __nv_bfloat16* __restrict__ A, int lda,
            const __nv_bfloat16* __restrict__ B,
            int N, int K,
            __nv_bfloat16* __restrict__ Cb, int ldcb)
{
    extern __shared__ __align__(16) char smem[];
    const uint32_t sb = smem_u32(smem);
    const uint32_t sa_base = sb;
    const uint32_t sbb_base = sb + 2 * A_BUF_B;

    const int tid  = threadIdx.x;
    const int wid  = tid >> 5, lane = tid & 31;
    const int wm   = wid & 1;
    const int wn   = wid >> 1;
    const int g    = lane >> 2;
    const int tg   = lane & 3;
    const int mt   = blockIdx.y;
    const int n0   = blockIdx.x * 256;

    float acc[4][8][4];
    #pragma unroll
    for (int mi = 0; mi < 4; mi++)
        #pragma unroll
        for (int ni = 0; ni < 8; ni++)
            #pragma unroll
            for (int q = 0; q < 4; q++) acc[mi][ni][q] = 0.0f;

    const int arow = tid >> 3, aseg = tid & 7;
    const int nkc = (K + 63) >> 6;

    {
        #pragma unroll
        for (int i = 0; i < 4; i++) {
            int row = arow + i * 32;
            int kk = aseg * 8;
            cp16(sa_base + row * 144 + aseg * 16,
                 A + (size_t)(mt * 128 + row) * lda + kk, kk < K);
        }
        #pragma unroll
        for (int i = 0; i < 8; i++) {
            int row = arow + i * 32;
            int kk = aseg * 8;
            int gn = n0 + row;
            cp16(sbb_base + row * 144 + aseg * 16,
                 B + (size_t)(gn < N ? gn : 0) * K + kk, gn < N && kk < K);
        }
        cp_commit();
    }

    for (int kc = 0; kc < nkc; kc++) {
        const int p = kc & 1;
        cp_wait0();
        __syncthreads();

        if (kc + 1 < nkc) {
            const int k0 = (kc + 1) << 6;
            const int q = p ^ 1;
            #pragma unroll
            for (int i = 0; i < 4; i++) {
                int row = arow + i * 32;
                int kk = k0 + aseg * 8;
                cp16(sa_base + q * A_BUF_B + row * 144 + aseg * 16,
                     A + (size_t)(mt * 128 + row) * lda + kk, kk < K);
            }
            #pragma unroll
            for (int i = 0; i < 8; i++) {
                int row = arow + i * 32;
                int kk = k0 + aseg * 8;
                int gn = n0 + row;
                cp16(sbb_base + q * B_BUF_B + row * 144 + aseg * 16,
                     B + (size_t)(gn < N ? gn : 0) * K + kk, gn < N && kk < K);
            }
            cp_commit();
        }

        const uint32_t abase = sa_base + p * A_BUF_B;
        const uint32_t bbase = sbb_base + p * B_BUF_B;

        #pragma unroll
        for (int ks = 0; ks < 4; ks++) {
            const int kb = ks * 16;
            uint32_t afrag[4][4];
            #pragma unroll
            for (int mi = 0; mi < 4; mi++) {
                int row = wm * 64 + mi * 16 + (lane & 15);
                int col = kb + (lane >> 4) * 8;
                ldsm_x4(afrag[mi][0], afrag[mi][1], afrag[mi][2], afrag[mi][3],
                        abase + row * 144 + col * 2);
            }
            #pragma unroll
            for (int nj = 0; nj < 4; nj++) {
                int row = wn * 64 + nj * 16 + ((lane >> 4) << 3) + (lane & 7);
                int col = kb + ((lane >> 3) & 1) * 8;
                uint32_t b0, b1, b2, b3;
                ldsm_x4(b0, b1, b2, b3, bbase + row * 144 + col * 2);
                uint32_t be[2] = {b0, b1};
                uint32_t bo[2] = {b2, b3};
                #pragma unroll
                for (int mi = 0; mi < 4; mi++) {
                    mma16816(acc[mi][2 * nj],     afrag[mi], be);
                    mma16816(acc[mi][2 * nj + 1], afrag[mi], bo);
                }
            }
        }
        __syncthreads();
    }

    #pragma unroll
    for (int mi = 0; mi < 4; mi++) {
        int row = mt * 128 + wm * 64 + mi * 16 + g;
        #pragma unroll
        for (int ni = 0; ni < 8; ni++) {
            int col = n0 + wn * 64 + ni * 8 + tg * 2;
            __nv_bfloat162 v0 = __floats2bfloat162_rn(acc[mi][ni][0], acc[mi][ni][1]);
            __nv_bfloat162 v1 = __floats2bfloat162_rn(acc[mi][ni][2], acc[mi][ni][3]);
            if (col + 1 < N) {
                *reinterpret_cast<uint32_t*>(Cb + (size_t)row * ldcb + col) =
                    *reinterpret_cast<uint32_t*>(&v0);
                *reinterpret_cast<uint32_t*>(Cb + (size_t)(row + 8) * ldcb + col) =
                    *reinterpret_cast<uint32_t*>(&v1);
            } else if (col < N) {
                Cb[(size_t)row * ldcb + col] = __low2bfloat16(v0);
                Cb[(size_t)(row + 8) * ldcb + col] = __low2bfloat16(v1);
            }
        }
    }
}

// ---------------- cluster pseudo-token logits ----------------
__global__ void cluster_logits_k(const __nv_bfloat16* __restrict__ y0b, int ystride,
                                 const float* __restrict__ cw,
                                 const float* __restrict__ cb,
                                 float* __restrict__ clog)
{
    int r = blockIdx.x;
    int t = threadIdx.x;   // 128
    float s0 = 0.f, s1 = 0.f, s2 = 0.f;
    const __nv_bfloat16* yr = y0b + (size_t)r * ystride;
    for (int d = t; d < 1024; d += 128) {
        float yv = __bfloat162float(yr[d]);
        s0 += yv * cw[d];
        s1 += yv * cw[1024 + d];
        s2 += yv * cw[2048 + d];
    }
    __shared__ float sh[3][128];
    sh[0][t] = s0; sh[1][t] = s1; sh[2][t] = s2;
    __syncthreads();
    for (int off = 64; off > 0; off >>= 1) {
        if (t < off) {
            sh[0][t] += sh[0][t + off];
            sh[1][t] += sh[1][t + off];
            sh[2][t] += sh[2][t + off];
        }
        __syncthreads();
    }
    if (t < 3) clog[r * 3 + t] = sh[t][0] + cb[t];
}

// ---------------- finalize LSE ----------------
__global__ void lse_fin_k(const float* __restrict__ gsum,
                          const float* __restrict__ clog,
                          float* __restrict__ lse)
{
    int i = blockIdx.x * blockDim.x + threadIdx.x;
    if (i >= ROWS * 4) return;
    int r = i >> 2, c = i & 3;
    float s = gsum[i];
    if (c == 0)
        s += expf(clog[r * 3]) + expf(clog[r * 3 + 1]) + expf(clog[r * 3 + 2]);
    lse[i] = logf(s);
}

// ---------------- fixup clusters 0/1 (cols [0,40000)) ----------------
__global__ void fixup_k(float* __restrict__ out,
                        const float* __restrict__ clog,
                        const float* __restrict__ lse)
{
    int r = blockIdx.y;
    float l0 = lse[r * 4 + 0];
    float adj0 = -l0;
    float adj1 = clog[r * 3 + 0] - l0 - lse[r * 4 + 1];
    float* p = out + (size_t)r * VOCAB;
    int base = blockIdx.x * 10000;
    for (int col = base + threadIdx.x; col < base + 10000; col += blockDim.x) {
        float adj = (col < 20000) ? adj0 : adj1;
        p[col] += adj;
    }
}

// ---------------- loss ----------------
__global__ void loss_k(const float* __restrict__ out,
                       const int* __restrict__ target,
                       float* __restrict__ dst)
{
    int t = threadIdx.x;
    float v = out[(size_t)t * VOCAB + target[t]];
    __shared__ float sh[512];
    sh[t] = v;
    __syncthreads();
    for (int off = 256; off > 0; off >>= 1) {
        if (t < off) sh[t] += sh[t + off];
        __syncthreads();
    }
    if (t == 0) *dst = -sh[0] / 512.0f;
}

// ---------------- launcher ----------------
extern "C" void kernel_launch(void* const* d_in, const int* in_sizes, int n_in,
                              void* d_out, int out_size)
{
    const float *hidden = 0, *cw = 0, *cb = 0;
    const float *proj0 = 0, *proj1 = 0, *proj2 = 0, *proj3 = 0;
    const float *W0 = 0, *W1 = 0, *W2 = 0, *W3 = 0;
    const float *b0 = 0, *b1 = 0, *b2 = 0, *b3 = 0;
    const int *target = 0;

    for (int i = 0; i < n_in; i++) {
        const void* p = d_in[i];
        switch (in_sizes[i]) {
            case 524288:   hidden = (const float*)p; break;
            case 512:      target = (const int*)p;   break;
            case 3072:     cw = (const float*)p;     break;
            case 3:        cb = (const float*)p;     break;
            case 1048576:  proj0 = (const float*)p;  break;
            case 20480000: W0 = (const float*)p;     break;
            case 262144:   proj1 = (const float*)p;  break;
            case 5120000:  W1 = (const float*)p;     break;
            case 65536:    proj2 = (const float*)p;  break;
            case 10240000: W2 = (const float*)p;     break;
            case 160000:   b2 = (const float*)p;     break;
            case 16384:    proj3 = (const float*)p;  break;
            case 1083760:  W3 = (const float*)p;     break;
            case 67735:    b3 = (const float*)p;     break;
            case 20000:    if (!b0) b0 = (const float*)p; else b1 = (const float*)p; break;
            default: break;
        }
    }
    float* out = (float*)d_out;

    __nv_bfloat16* bf = nullptr;
    cudaGetSymbolAddress((void**)&bf, g_bf);
    float* f32s = nullptr;
    cudaGetSymbolAddress((void**)&f32s, g_f32);
    float* gsum = nullptr;
    cudaGetSymbolAddress((void**)&gsum, g_sum);
    float* clog = f32s;
    float* lse  = f32s + ROWS * 3;

    cudaFuncSetAttribute(proj_gemm_k, cudaFuncAttributeMaxDynamicSharedMemorySize, SM_GEMM);
    cudaFuncSetAttribute(logits_k, cudaFuncAttributeMaxDynamicSharedMemorySize, SM_LOG);

    zero_k<<<2, 1024>>>(gsum);
    conv_all_k<<<2368, 256>>>(W0, W1, W2, W3, proj0, proj1, proj2, proj3, hidden);

    // packed projection GEMM: Y[512,1360] = hidden @ [proj0..3]^T
    proj_gemm_k<<<dim3(6, 4), 256, SM_GEMM>>>(bf + B_H, 1024, bf + B_P0, 1360, 1024,
        bf + B_Y, 1360);

    cluster_logits_k<<<ROWS, 128>>>(bf + B_Y, 1360, cw, cb, clog);

    // pass 1: all clusters — raw store for c0/c1, exp sums for all
    logits_k<<<dim3(4185, 4), 256, SM_LOG>>>(0, out, b0, b1, b2, b3, gsum,
                                             nullptr, nullptr);
    lse_fin_k<<<2, 1024>>>(gsum, clog, lse);

    // pass 2: clusters 2/3 recompute + adjusted store
    logits_k<<<dim3(3559, 4), 256, SM_LOG>>>(1, out, b0, b1, b2, b3, nullptr,
                                             clog, lse);
    // patch clusters 0/1 in place
    fixup_k<<<dim3(4, ROWS), 256>>>(out, clog, lse);

    long total = (long)ROWS * VOCAB;
    if ((long)out_size > total)
        loss_k<<<1, ROWS>>>(out, target, out + total);
}

// round 15
// speedup vs baseline: 1.1502x; 1.1502x over previous
#include <cuda_runtime.h>
#include <cuda_bf16.h>
#include <math.h>
#include <stdint.h>

static constexpr int VOCAB = 267735;
static constexpr int ROWS  = 512;

// bf16 scratch element offsets (convert region, then packed Y)
static constexpr size_t B_W0 = 0;
static constexpr size_t B_W1 = 20480000;
static constexpr size_t B_W2 = 25600000;
static constexpr size_t B_W3 = 35840000;
static constexpr size_t B_P0 = 36923760;   // packed projections (1360 rows x 1024)
static constexpr size_t B_H  = 38316400;
static constexpr size_t B_CONV_END = 38840688;
static constexpr size_t B_Y  = 38840688;   // packed Y [512 x 1360]
static constexpr size_t B_END = 38840688 + 512 * 1360;

__device__ __align__(16) __nv_bfloat16 g_bf[B_END];
__device__ __align__(16) float g_f32[ROWS * 3 + ROWS * 4];   // clog[512*3], lse[512*4]
__device__ __align__(16) float g_sum[ROWS * 4];              // per-(row,cluster) exp sums

// ---------------- fast exp (FMA-only, |x| < ~20, no clamp) ----------------
__device__ __forceinline__ float fast_exp(float x) {
    float y = x * 1.4426950408889634f;
    float t = y + 12582912.0f;                       // magic round-to-nearest
    int   n = __float_as_int(t) - 0x4B400000;
    float f = y - (t - 12582912.0f);                 // f in [-0.5, 0.5]
    float u = f * 0.6931471805599453f;               // |u| <= 0.347
    float p = 1.0f + u*(1.0f + u*(0.5f + u*(0.16666667f + u*0.041666667f)));
    return p * __int_as_float((n + 127) << 23);
}

// ---------------- zero the sums ----------------
__global__ void zero_k(float* __restrict__ gsum) {
    int i = blockIdx.x * blockDim.x + threadIdx.x;
    if (i < ROWS * 4) gsum[i] = 0.0f;
}

// ---------------- fused fp32 -> bf16 convert ----------------
__global__ void conv_all_k(const float* __restrict__ w0, const float* __restrict__ w1,
                           const float* __restrict__ w2, const float* __restrict__ w3,
                           const float* __restrict__ p0, const float* __restrict__ p1,
                           const float* __restrict__ p2, const float* __restrict__ p3,
                           const float* __restrict__ hh)
{
    const size_t e1 = 20480000, e2 = 25600000, e3 = 35840000, e4 = 36923760;
    const size_t e5 = 37972336, e6 = 38234480, e7 = 38300016, e8 = 38316400;
    const size_t nchunks = B_CONV_END / 8;
    size_t stride = (size_t)gridDim.x * blockDim.x;
    for (size_t c = (size_t)blockIdx.x * blockDim.x + threadIdx.x; c < nchunks; c += stride) {
        size_t e = c * 8;
        const float* src;
        size_t base;
        if      (e < e1) { src = w0; base = 0;  }
        else if (e < e2) { src = w1; base = e1; }
        else if (e < e3) { src = w2; base = e2; }
        else if (e < e4) { src = w3; base = e3; }
        else if (e < e5) { src = p0; base = e4; }
        else if (e < e6) { src = p1; base = e5; }
        else if (e < e7) { src = p2; base = e6; }
        else if (e < e8) { src = p3; base = e7; }
        else             { src = hh; base = e8; }
        const float4* s = reinterpret_cast<const float4*>(src + (e - base));
        float4 v0 = s[0];
        float4 v1 = s[1];
        __nv_bfloat162 a0 = __floats2bfloat162_rn(v0.x, v0.y);
        __nv_bfloat162 a1 = __floats2bfloat162_rn(v0.z, v0.w);
        __nv_bfloat162 a2 = __floats2bfloat162_rn(v1.x, v1.y);
        __nv_bfloat162 a3 = __floats2bfloat162_rn(v1.z, v1.w);
        uint4 u;
        u.x = *reinterpret_cast<uint32_t*>(&a0);
        u.y = *reinterpret_cast<uint32_t*>(&a1);
        u.z = *reinterpret_cast<uint32_t*>(&a2);
        u.w = *reinterpret_cast<uint32_t*>(&a3);
        *reinterpret_cast<uint4*>(g_bf + e) = u;
    }
}

// ---------------- common PTX helpers ----------------
__device__ __forceinline__ uint32_t smem_u32(const void* p) {
    uint32_t a;
    asm("{ .reg .u64 t; cvta.to.shared.u64 t, %1; cvt.u32.u64 %0, t; }" : "=r"(a) : "l"(p));
    return a;
}
__device__ __forceinline__ void mma16816(float* c, const uint32_t* a, const uint32_t* b) {
    asm volatile(
        "mma.sync.aligned.m16n8k16.row.col.f32.bf16.bf16.f32 "
        "{%0,%1,%2,%3}, {%4,%5,%6,%7}, {%8,%9}, {%0,%1,%2,%3};"
        : "+f"(c[0]), "+f"(c[1]), "+f"(c[2]), "+f"(c[3])
        : "r"(a[0]), "r"(a[1]), "r"(a[2]), "r"(a[3]), "r"(b[0]), "r"(b[1]));
}
__device__ __forceinline__ void ldsm_x4(uint32_t& r0, uint32_t& r1, uint32_t& r2, uint32_t& r3,
                                        uint32_t addr) {
    asm volatile("ldmatrix.sync.aligned.m8n8.x4.shared.b16 {%0,%1,%2,%3}, [%4];"
        : "=r"(r0), "=r"(r1), "=r"(r2), "=r"(r3) : "r"(addr));
}
__device__ __forceinline__ void cp16(uint32_t dst, const void* src, bool valid) {
    int sz = valid ? 16 : 0;
    asm volatile("cp.async.cg.shared.global [%0], [%1], 16, %2;"
        :: "r"(dst), "l"(src), "r"(sz) : "memory");
}
__device__ __forceinline__ void cp_commit() {
    asm volatile("cp.async.commit_group;" ::: "memory");
}
__device__ __forceinline__ void cp_wait0() {
    asm volatile("cp.async.wait_group 0;" ::: "memory");
}

// ================= fused logit GEMM (R12 config: CTA 128x128, 2 CTAs/SM) =========
// mode 0 (grid.x = 2094, all clusters): GEMM; store RAW logits for clusters 0/1;
//        accumulate plain exp-sums for all clusters via atomicAdd.
// mode 1 (grid.x = 1780, clusters 2/3): GEMM recompute; store adjusted log-probs.
static constexpr int TILE_BUF = 128 * 144;              // 18432 bytes
static constexpr int SM_LOG   = 4 * TILE_BUF;           // 73728

__global__ void __launch_bounds__(256, 2)
logits_k(int mode,
         float* __restrict__ out,
         const float* __restrict__ bias0, const float* __restrict__ bias1,
         const float* __restrict__ bias2, const float* __restrict__ bias3,
         float* __restrict__ gsum,
         const float* __restrict__ clog,
         const float* __restrict__ lse)
{
    const int    ct_base[5] = {0, 157, 314, 1564, 2094};
    const int    ct_k[4]    = {1024, 256, 64, 16};
    const int    ct_aoff[4] = {0, 1024, 1280, 1344};
    const size_t ct_boff[4] = {B_W0, B_W1, B_W2, B_W3};
    const int    ct_n[4]    = {20000, 20000, 160000, 67735};
    const int    ct_col[4]  = {0, 20000, 40000, 200000};

    extern __shared__ __align__(16) char smem[];
    const uint32_t sb = smem_u32(smem);

    const int t = blockIdx.x + ((mode == 1) ? 314 : 0);
    int c;
    if      (t < ct_base[1]) c = 0;
    else if (t < ct_base[2]) c = 1;
    else if (t < ct_base[3]) c = 2;
    else                     c = 3;
    const int tl = t - ct_base[c];
    const int n0 = tl * 128;
    const int K  = ct_k[c];
    const int N  = ct_n[c];
    const int mt = blockIdx.y;
    const bool full = (n0 + 128 <= N);
    const __nv_bfloat16* A = g_bf + B_Y + ct_aoff[c];
    const __nv_bfloat16* B = g_bf + ct_boff[c];
    const float* bias = (c == 0) ? bias0 : (c == 1) ? bias1 : (c == 2) ? bias2 : bias3;

    const int tid  = threadIdx.x;
    const int wid  = tid >> 5, lane = tid & 31;
    const int wm   = wid & 3;
    const int wn   = wid >> 2;
    const int g    = lane >> 2;
    const int tg   = lane & 3;

    float acc[2][8][4];
    #pragma unroll
    for (int mi = 0; mi < 2; mi++)
        #pragma unroll
        for (int ni = 0; ni < 8; ni++)
            #pragma unroll
            for (int q = 0; q < 4; q++) acc[mi][ni][q] = 0.0f;

    const int lrow = tid >> 1;
    const int lseg = (tid & 1) * 4;
    const int nkc = (K + 63) >> 6;

    // prologue
    {
        #pragma unroll
        for (int i = 0; i < 4; i++) {
            int kk = (lseg + i) * 8;
            cp16(sb + lrow * 144 + (lseg + i) * 16,
                 A + (size_t)(mt * 128 + lrow) * 1360 + kk, kk < K);
        }
        int gn = n0 + lrow;
        #pragma unroll
        for (int i = 0; i < 4; i++) {
            int kk = (lseg + i) * 8;
            cp16(sb + 2 * TILE_BUF + lrow * 144 + (lseg + i) * 16,
                 B + (size_t)(gn < N ? gn : 0) * K + kk, gn < N && kk < K);
        }
        cp_commit();
    }

    for (int kc = 0; kc < nkc; kc++) {
        const int p = kc & 1;
        cp_wait0();
        __syncthreads();

        if (kc + 1 < nkc) {
            const int k0 = (kc + 1) << 6;
            const int q = p ^ 1;
            #pragma unroll
            for (int i = 0; i < 4; i++) {
                int kk = k0 + (lseg + i) * 8;
                cp16(sb + q * TILE_BUF + lrow * 144 + (lseg + i) * 16,
                     A + (size_t)(mt * 128 + lrow) * 1360 + kk, kk < K);
            }
            int gn = n0 + lrow;
            #pragma unroll
            for (int i = 0; i < 4; i++) {
                int kk = k0 + (lseg + i) * 8;
                cp16(sb + (2 + q) * TILE_BUF + lrow * 144 + (lseg + i) * 16,
                     B + (size_t)(gn < N ? gn : 0) * K + kk, gn < N && kk < K);
            }
            cp_commit();
        }

        const uint32_t abase = sb + p * TILE_BUF;
        const uint32_t bbase = sb + (2 + p) * TILE_BUF;

        #pragma unroll
        for (int ks = 0; ks < 4; ks++) {
            const int kb = ks * 16;
            uint32_t afrag[2][4];
            #pragma unroll
            for (int mi = 0; mi < 2; mi++) {
                int row = wm * 32 + mi * 16 + (lane & 15);
                int col = kb + (lane >> 4) * 8;
                ldsm_x4(afrag[mi][0], afrag[mi][1], afrag[mi][2], afrag[mi][3],
                        abase + row * 144 + col * 2);
            }
            #pragma unroll
            for (int nj = 0; nj < 4; nj++) {
                int row = wn * 64 + nj * 16 + ((lane >> 4) << 3) + (lane & 7);
                int col = kb + ((lane >> 3) & 1) * 8;
                uint32_t b0, b1, b2, b3;
                ldsm_x4(b0, b1, b2, b3, bbase + row * 144 + col * 2);
                uint32_t be[2] = {b0, b1};
                uint32_t bo[2] = {b2, b3};
                #pragma unroll
                for (int mi = 0; mi < 2; mi++) {
                    mma16816(acc[mi][2 * nj],     afrag[mi], be);
                    mma16816(acc[mi][2 * nj + 1], afrag[mi], bo);
                }
            }
        }
        __syncthreads();
    }

    // bias fold (guard-free when tile is interior)
    if (full) {
        #pragma unroll
        for (int ni = 0; ni < 8; ni++) {
            #pragma unroll
            for (int q = 0; q < 2; q++) {
                int col = n0 + wn * 64 + ni * 8 + tg * 2 + q;
                float bvq = bias[col];
                #pragma unroll
                for (int mi = 0; mi < 2; mi++) {
                    acc[mi][ni][q]     += bvq;
                    acc[mi][ni][q + 2] += bvq;
                }
            }
        }
    } else {
        #pragma unroll
        for (int ni = 0; ni < 8; ni++) {
            #pragma unroll
            for (int q = 0; q < 2; q++) {
                int col = n0 + wn * 64 + ni * 8 + tg * 2 + q;
                float bvq = (col < N) ? bias[col] : 0.0f;
                #pragma unroll
                for (int mi = 0; mi < 2; mi++) {
                    acc[mi][ni][q]     += bvq;
                    acc[mi][ni][q + 2] += bvq;
                }
            }
        }
    }

    float* stage = reinterpret_cast<float*>(smem);                 // [128][132]
    float* saux  = reinterpret_cast<float*>(smem) + 128 * 132;     // [256]

    if (mode == 0) {
        // ---- plain exp sums ----
        #pragma unroll
        for (int mi = 0; mi < 2; mi++) {
            int rl = wm * 32 + mi * 16 + g;
            float s_lo = 0.0f, s_hi = 0.0f;
            if (full) {
                #pragma unroll
                for (int ni = 0; ni < 8; ni++) {
                    s_lo += fast_exp(acc[mi][ni][0]);
                    s_hi += fast_exp(acc[mi][ni][2]);
                    s_lo += fast_exp(acc[mi][ni][1]);
                    s_hi += fast_exp(acc[mi][ni][3]);
                }
            } else {
                #pragma unroll
                for (int ni = 0; ni < 8; ni++) {
                    int col = n0 + wn * 64 + ni * 8 + tg * 2;
                    if (col < N) {
                        s_lo += fast_exp(acc[mi][ni][0]);
                        s_hi += fast_exp(acc[mi][ni][2]);
                    }
                    if (col + 1 < N) {
                        s_lo += fast_exp(acc[mi][ni][1]);
                        s_hi += fast_exp(acc[mi][ni][3]);
                    }
                }
            }
            s_lo += __shfl_xor_sync(0xffffffff, s_lo, 1);
            s_lo += __shfl_xor_sync(0xffffffff, s_lo, 2);
            s_hi += __shfl_xor_sync(0xffffffff, s_hi, 1);
            s_hi += __shfl_xor_sync(0xffffffff, s_hi, 2);
            if (tg == 0) {
                saux[rl * 2 + wn] = s_lo;
                saux[(rl + 8) * 2 + wn] = s_hi;
            }
        }
        if (c < 2) {
            #pragma unroll
            for (int mi = 0; mi < 2; mi++) {
                int rl = wm * 32 + mi * 16 + g;
                #pragma unroll
                for (int ni = 0; ni < 8; ni++) {
                    int cl = wn * 64 + ni * 8 + tg * 2;
                    stage[rl * 132 + cl]           = acc[mi][ni][0];
                    stage[rl * 132 + cl + 1]       = acc[mi][ni][1];
                    stage[(rl + 8) * 132 + cl]     = acc[mi][ni][2];
                    stage[(rl + 8) * 132 + cl + 1] = acc[mi][ni][3];
                }
            }
        }
        __syncthreads();
        if (tid < 128) {
            float s = saux[tid * 2] + saux[tid * 2 + 1];
            atomicAdd(&gsum[(mt * 128 + tid) * 4 + c], s);
        }
        if (c < 2) {
            if (full) {
                #pragma unroll 4
                for (int it = 0; it < 64; it++) {
                    int row = (it & 15) * 8 + wid;
                    int col = (it >> 4) * 32 + lane;
                    out[(size_t)(mt * 128 + row) * VOCAB + ct_col[c] + n0 + col] =
                        stage[row * 132 + col];
                }
            } else {
                #pragma unroll 4
                for (int it = 0; it < 64; it++) {
                    int row = (it & 15) * 8 + wid;
                    int col = (it >> 4) * 32 + lane;
                    int gcol = n0 + col;
                    if (gcol < N)
                        out[(size_t)(mt * 128 + row) * VOCAB + ct_col[c] + gcol] =
                            stage[row * 132 + col];
                }
            }
        }
    } else {
        // ---- pass 2 (clusters 2/3): adjusted log-prob store (streaming) ----
        if (tid < 128) {
            int grow = mt * 128 + tid;
            float l0 = lse[grow * 4 + 0];
            saux[tid] = clog[grow * 3 + (c - 1)] - l0 - lse[grow * 4 + c];
        }
        #pragma unroll
        for (int mi = 0; mi < 2; mi++) {
            int rl = wm * 32 + mi * 16 + g;
            #pragma unroll
            for (int ni = 0; ni < 8; ni++) {
                int cl = wn * 64 + ni * 8 + tg * 2;
                stage[rl * 132 + cl]           = acc[mi][ni][0];
                stage[rl * 132 + cl + 1]       = acc[mi][ni][1];
                stage[(rl + 8) * 132 + cl]     = acc[mi][ni][2];
                stage[(rl + 8) * 132 + cl + 1] = acc[mi][ni][3];
            }
        }
        __syncthreads();
        if (full) {
            #pragma unroll 4
            for (int it = 0; it < 64; it++) {
                int row = (it & 15) * 8 + wid;
                int col = (it >> 4) * 32 + lane;
                float v = stage[row * 132 + col] + saux[row];
                __stcs(&out[(size_t)(mt * 128 + row) * VOCAB + ct_col[c] + n0 + col], v);
            }
        } else {
            #pragma unroll 4
            for (int it = 0; it < 64; it++) {
                int row = (it & 15) * 8 + wid;
                int col = (it >> 4) * 32 + lane;
                int gcol = n0 + col;
                if (gcol < N) {
                    float v = stage[row * 132 + col] + saux[row];
                    __stcs(&out[(size_t)(mt * 128 + row) * VOCAB + ct_col[c] + gcol], v);
                }
            }
        }
    }
}

// ================= projection GEMM (bf16 out), 128x256 tile, 8 warps 2Mx4N =================
static constexpr int A_BUF_B = 128 * 144;
static constexpr int B_BUF_B = 256 * 144;
static constexpr int SM_GEMM = 2 * A_BUF_B + 2 * B_BUF_B;

__global__ void __launch_bounds__(256)
proj_gemm_k(const __nv_bfloat16* __restrict__ A, int lda,
            const __nv_bfloat16* __restrict__ B,
            int N, int K,
            __nv_bfloat16* __restrict__ Cb, int ldcb)
{
    extern __shared__ __align__(16) char smem[];
    const uint32_t sb = smem_u32(smem);
    const uint32_t sa_base = sb;
    const uint32_t sbb_base = sb + 2 * A_BUF_B;

    const int tid  = threadIdx.x;
    const int wid  = tid >> 5, lane = tid & 31;
    const int wm   = wid & 1;
    const int wn   = wid >> 1;
    const int g    = lane >> 2;
    const int tg   = lane & 3;
    const int mt   = blockIdx.y;
    const int n0   = blockIdx.x * 256;

    float acc[4][8][4];
    #pragma unroll
    for (int mi = 0; mi < 4; mi++)
        #pragma unroll
        for (int ni = 0; ni < 8; ni++)
            #pragma unroll
            for (int q = 0; q < 4; q++) acc[mi][ni][q] = 0.0f;

    const int arow = tid >> 3, aseg = tid & 7;
    const int nkc = (K + 63) >> 6;

    {
        #pragma unroll
        for (int i = 0; i < 4; i++) {
            int row = arow + i * 32;
            int kk = aseg * 8;
            cp16(sa_base + row * 144 + aseg * 16,
                 A + (size_t)(mt * 128 + row) * lda + kk, kk < K);
        }
        #pragma unroll
        for (int i = 0; i < 8; i++) {
            int row = arow + i * 32;
            int kk = aseg * 8;
            int gn = n0 + row;
            cp16(sbb_base + row * 144 + aseg * 16,
                 B + (size_t)(gn < N ? gn : 0) * K + kk, gn < N && kk < K);
        }
        cp_commit();
    }

    for (int kc = 0; kc < nkc; kc++) {
        const int p = kc & 1;
        cp_wait0();
        __syncthreads();

        if (kc + 1 < nkc) {
            const int k0 = (kc + 1) << 6;
            const int q = p ^ 1;
            #pragma unroll
            for (int i = 0; i < 4; i++) {
                int row = arow + i * 32;
                int kk = k0 + aseg * 8;
                cp16(sa_base + q * A_BUF_B + row * 144 + aseg * 16,
                     A + (size_t)(mt * 128 + row) * lda + kk, kk < K);
            }
            #pragma unroll
            for (int i = 0; i < 8; i++) {
                int row = arow + i * 32;
                int kk = k0 + aseg * 8;
                int gn = n0 + row;
                cp16(sbb_base + q * B_BUF_B + row * 144 + aseg * 16,
                     B + (size_t)(gn < N ? gn : 0) * K + kk, gn < N && kk < K);
            }
            cp_commit();
        }

        const uint32_t abase = sa_base + p * A_BUF_B;
        const uint32_t bbase = sbb_base + p * B_BUF_B;

        #pragma unroll
        for (int ks = 0; ks < 4; ks++) {
            const int kb = ks * 16;
            uint32_t afrag[4][4];
            #pragma unroll
            for (int mi = 0; mi < 4; mi++) {
                int row = wm * 64 + mi * 16 + (lane & 15);
                int col = kb + (lane >> 4) * 8;
                ldsm_x4(afrag[mi][0], afrag[mi][1], afrag[mi][2], afrag[mi][3],
                        abase + row * 144 + col * 2);
            }
            #pragma unroll
            for (int nj = 0; nj < 4; nj++) {
                int row = wn * 64 + nj * 16 + ((lane >> 4) << 3) + (lane & 7);
                int col = kb + ((lane >> 3) & 1) * 8;
                uint32_t b0, b1, b2, b3;
                ldsm_x4(b0, b1, b2, b3, bbase + row * 144 + col * 2);
                uint32_t be[2] = {b0, b1};
                uint32_t bo[2] = {b2, b3};
                #pragma unroll
                for (int mi = 0; mi < 4; mi++) {
                    mma16816(acc[mi][2 * nj],     afrag[mi], be);
                    mma16816(acc[mi][2 * nj + 1], afrag[mi], bo);
                }
            }
        }
        __syncthreads();
    }

    #pragma unroll
    for (int mi = 0; mi < 4; mi++) {
        int row = mt * 128 + wm * 64 + mi * 16 + g;
        #pragma unroll
        for (int ni = 0; ni < 8; ni++) {
            int col = n0 + wn * 64 + ni * 8 + tg * 2;
            __nv_bfloat162 v0 = __floats2bfloat162_rn(acc[mi][ni][0], acc[mi][ni][1]);
            __nv_bfloat162 v1 = __floats2bfloat162_rn(acc[mi][ni][2], acc[mi][ni][3]);
            if (col + 1 < N) {
                *reinterpret_cast<uint32_t*>(Cb + (size_t)row * ldcb + col) =
                    *reinterpret_cast<uint32_t*>(&v0);
                *reinterpret_cast<uint32_t*>(Cb + (size_t)(row + 8) * ldcb + col) =
                    *reinterpret_cast<uint32_t*>(&v1);
            } else if (col < N) {
                Cb[(size_t)row * ldcb + col] = __low2bfloat16(v0);
                Cb[(size_t)(row + 8) * ldcb + col] = __low2bfloat16(v1);
            }
        }
    }
}

// ---------------- cluster pseudo-token logits ----------------
__global__ void cluster_logits_k(const __nv_bfloat16* __restrict__ y0b, int ystride,
                                 const float* __restrict__ cw,
                                 const float* __restrict__ cb,
                                 float* __restrict__ clog)
{
    int r = blockIdx.x;
    int t = threadIdx.x;   // 128
    float s0 = 0.f, s1 = 0.f, s2 = 0.f;
    const __nv_bfloat16* yr = y0b + (size_t)r * ystride;
    for (int d = t; d < 1024; d += 128) {
        float yv = __bfloat162float(yr[d]);
        s0 += yv * cw[d];
        s1 += yv * cw[1024 + d];
        s2 += yv * cw[2048 + d];
    }
    __shared__ float sh[3][128];
    sh[0][t] = s0; sh[1][t] = s1; sh[2][t] = s2;
    __syncthreads();
    for (int off = 64; off > 0; off >>= 1) {
        if (t < off) {
            sh[0][t] += sh[0][t + off];
            sh[1][t] += sh[1][t + off];
            sh[2][t] += sh[2][t + off];
        }
        __syncthreads();
    }
    if (t < 3) clog[r * 3 + t] = sh[t][0] + cb[t];
}

// ---------------- finalize LSE ----------------
__global__ void lse_fin_k(const float* __restrict__ gsum,
                          const float* __restrict__ clog,
                          float* __restrict__ lse)
{
    int i = blockIdx.x * blockDim.x + threadIdx.x;
    if (i >= ROWS * 4) return;
    int r = i >> 2, c = i & 3;
    float s = gsum[i];
    if (c == 0)
        s += expf(clog[r * 3]) + expf(clog[r * 3 + 1]) + expf(clog[r * 3 + 2]);
    lse[i] = logf(s);
}

// ---------------- fixup clusters 0/1 (cols [0,40000)), scalar (VOCAB odd!) ----------------
__global__ void fixup_k(float* __restrict__ out,
                        const float* __restrict__ clog,
                        const float* __restrict__ lse)
{
    int r = blockIdx.y;
    float l0 = lse[r * 4 + 0];
    float adj0 = -l0;
    float adj1 = clog[r * 3 + 0] - l0 - lse[r * 4 + 1];
    float* p = out + (size_t)r * VOCAB;
    int base = blockIdx.x * 10000;
    for (int col = base + threadIdx.x; col < base + 10000; col += blockDim.x) {
        float adj = (col < 20000) ? adj0 : adj1;
        p[col] += adj;
    }
}

// ---------------- loss ----------------
__global__ void loss_k(const float* __restrict__ out,
                       const int* __restrict__ target,
                       float* __restrict__ dst)
{
    int t = threadIdx.x;
    float v = out[(size_t)t * VOCAB + target[t]];
    __shared__ float sh[512];
    sh[t] = v;
    __syncthreads();
    for (int off = 256; off > 0; off >>= 1) {
        if (t < off) sh[t] += sh[t + off];
        __syncthreads();
    }
    if (t == 0) *dst = -sh[0] / 512.0f;
}

// ---------------- launcher ----------------
extern "C" void kernel_launch(void* const* d_in, const int* in_sizes, int n_in,
                              void* d_out, int out_size)
{
    const float *hidden = 0, *cw = 0, *cb = 0;
    const float *proj0 = 0, *proj1 = 0, *proj2 = 0, *proj3 = 0;
    const float *W0 = 0, *W1 = 0, *W2 = 0, *W3 = 0;
    const float *b0 = 0, *b1 = 0, *b2 = 0, *b3 = 0;
    const int *target = 0;

    for (int i = 0; i < n_in; i++) {
        const void* p = d_in[i];
        switch (in_sizes[i]) {
            case 524288:   hidden = (const float*)p; break;
            case 512:      target = (const int*)p;   break;
            case 3072:     cw = (const float*)p;     break;
            case 3:        cb = (const float*)p;     break;
            case 1048576:  proj0 = (const float*)p;  break;
            case 20480000: W0 = (const float*)p;     break;
            case 262144:   proj1 = (const float*)p;  break;
            case 5120000:  W1 = (const float*)p;     break;
            case 65536:    proj2 = (const float*)p;  break;
            case 10240000: W2 = (const float*)p;     break;
            case 160000:   b2 = (const float*)p;     break;
            case 16384:    proj3 = (const float*)p;  break;
            case 1083760:  W3 = (const float*)p;     break;
            case 67735:    b3 = (const float*)p;     break;
            case 20000:    if (!b0) b0 = (const float*)p; else b1 = (const float*)p; break;
            default: break;
        }
    }
    float* out = (float*)d_out;

    __nv_bfloat16* bf = nullptr;
    cudaGetSymbolAddress((void**)&bf, g_bf);
    float* f32s = nullptr;
    cudaGetSymbolAddress((void**)&f32s, g_f32);
    float* gsum = nullptr;
    cudaGetSymbolAddress((void**)&gsum, g_sum);
    float* clog = f32s;
    float* lse  = f32s + ROWS * 3;

    cudaFuncSetAttribute(proj_gemm_k, cudaFuncAttributeMaxDynamicSharedMemorySize, SM_GEMM);
    cudaFuncSetAttribute(logits_k, cudaFuncAttributeMaxDynamicSharedMemorySize, SM_LOG);

    zero_k<<<2, 1024>>>(gsum);
    conv_all_k<<<2368, 256>>>(W0, W1, W2, W3, proj0, proj1, proj2, proj3, hidden);

    // packed projection GEMM: Y[512,1360] = hidden @ [proj0..3]^T
    proj_gemm_k<<<dim3(6, 4), 256, SM_GEMM>>>(bf + B_H, 1024, bf + B_P0, 1360, 1024,
        bf + B_Y, 1360);

    cluster_logits_k<<<ROWS, 128>>>(bf + B_Y, 1360, cw, cb, clog);

    // pass 1: all clusters — raw store for c0/c1, exp sums for all
    logits_k<<<dim3(2094, 4), 256, SM_LOG>>>(0, out, b0, b1, b2, b3, gsum,
                                             nullptr, nullptr);
    lse_fin_k<<<2, 1024>>>(gsum, clog, lse);

    // pass 2: clusters 2/3 recompute + adjusted store
    logits_k<<<dim3(1780, 4), 256, SM_LOG>>>(1, out, b0, b1, b2, b3, nullptr,
                                             clog, lse);
    // patch clusters 0/1 in place (scalar — row bases are not 16B-aligned)
    fixup_k<<<dim3(4, ROWS), 256>>>(out, clog, lse);

    long total = (long)ROWS * VOCAB;
    if ((long)out_size > total)
        loss_k<<<1, ROWS>>>(out, target, out + total);
}

// round 16
// speedup vs baseline: 1.2236x; 1.0638x over previous
#include <cuda_runtime.h>
#include <cuda_bf16.h>
#include <math.h>
#include <stdint.h>

static constexpr int VOCAB = 267735;
static constexpr int ROWS  = 512;

// bf16 scratch element offsets
static constexpr size_t B_W0 = 0;
static constexpr size_t B_W1 = 20480000;
static constexpr size_t B_W2 = 25600000;
static constexpr size_t B_W3 = 35840000;
static constexpr size_t B_P0 = 36923760;
static constexpr size_t B_H  = 38316400;
static constexpr size_t B_CONV_END = 38840688;
static constexpr size_t B_Y  = 38840688;
static constexpr size_t B_END = 38840688 + 512 * 1360;

__device__ __align__(16) __nv_bfloat16 g_bf[B_END];
__device__ __align__(16) float g_f32[ROWS * 3 + ROWS * 4];
__device__ __align__(16) float g_sum[ROWS * 4];

// ---------------- fast exp ----------------
__device__ __forceinline__ float fast_exp(float x) {
    float y = x * 1.4426950408889634f;
    float t = y + 12582912.0f;
    int   n = __float_as_int(t) - 0x4B400000;
    float f = y - (t - 12582912.0f);
    float u = f * 0.6931471805599453f;
    float p = 1.0f + u*(1.0f + u*(0.5f + u*(0.16666667f + u*0.041666667f)));
    return p * __int_as_float((n + 127) << 23);
}

// ---------------- fused convert + gsum zero ----------------
__global__ void conv_all_k(const float* __restrict__ w0, const float* __restrict__ w1,
                           const float* __restrict__ w2, const float* __restrict__ w3,
                           const float* __restrict__ p0, const float* __restrict__ p1,
                           const float* __restrict__ p2, const float* __restrict__ p3,
                           const float* __restrict__ hh)
{
    int gi = blockIdx.x * blockDim.x + threadIdx.x;
    if (gi < ROWS * 4) g_sum[gi] = 0.0f;

    const size_t e1 = 20480000, e2 = 25600000, e3 = 35840000, e4 = 36923760;
    const size_t e5 = 37972336, e6 = 38234480, e7 = 38300016, e8 = 38316400;
    const size_t nchunks = B_CONV_END / 8;
    size_t stride = (size_t)gridDim.x * blockDim.x;
    for (size_t c = (size_t)gi; c < nchunks; c += stride) {
        size_t e = c * 8;
        const float* src;
        size_t base;
        if      (e < e1) { src = w0; base = 0;  }
        else if (e < e2) { src = w1; base = e1; }
        else if (e < e3) { src = w2; base = e2; }
        else if (e < e4) { src = w3; base = e3; }
        else if (e < e5) { src = p0; base = e4; }
        else if (e < e6) { src = p1; base = e5; }
        else if (e < e7) { src = p2; base = e6; }
        else if (e < e8) { src = p3; base = e7; }
        else             { src = hh; base = e8; }
        const float4* s = reinterpret_cast<const float4*>(src + (e - base));
        float4 v0 = s[0];
        float4 v1 = s[1];
        __nv_bfloat162 a0 = __floats2bfloat162_rn(v0.x, v0.y);
        __nv_bfloat162 a1 = __floats2bfloat162_rn(v0.z, v0.w);
        __nv_bfloat162 a2 = __floats2bfloat162_rn(v1.x, v1.y);
        __nv_bfloat162 a3 = __floats2bfloat162_rn(v1.z, v1.w);
        uint4 u;
        u.x = *reinterpret_cast<uint32_t*>(&a0);
        u.y = *reinterpret_cast<uint32_t*>(&a1);
        u.z = *reinterpret_cast<uint32_t*>(&a2);
        u.w = *reinterpret_cast<uint32_t*>(&a3);
        *reinterpret_cast<uint4*>(g_bf + e) = u;
    }
}

// ---------------- PTX helpers ----------------
__device__ __forceinline__ uint32_t smem_u32(const void* p) {
    uint32_t a;
    asm("{ .reg .u64 t; cvta.to.shared.u64 t, %1; cvt.u32.u64 %0, t; }" : "=r"(a) : "l"(p));
    return a;
}
__device__ __forceinline__ void mma16816(float* c, const uint32_t* a, const uint32_t* b) {
    asm volatile(
        "mma.sync.aligned.m16n8k16.row.col.f32.bf16.bf16.f32 "
        "{%0,%1,%2,%3}, {%4,%5,%6,%7}, {%8,%9}, {%0,%1,%2,%3};"
        : "+f"(c[0]), "+f"(c[1]), "+f"(c[2]), "+f"(c[3])
        : "r"(a[0]), "r"(a[1]), "r"(a[2]), "r"(a[3]), "r"(b[0]), "r"(b[1]));
}
__device__ __forceinline__ void ldsm_x4(uint32_t& r0, uint32_t& r1, uint32_t& r2, uint32_t& r3,
                                        uint32_t addr) {
    asm volatile("ldmatrix.sync.aligned.m8n8.x4.shared.b16 {%0,%1,%2,%3}, [%4];"
        : "=r"(r0), "=r"(r1), "=r"(r2), "=r"(r3) : "r"(addr));
}
__device__ __forceinline__ void cp16(uint32_t dst, const void* src, bool valid) {
    int sz = valid ? 16 : 0;
    asm volatile("cp.async.cg.shared.global [%0], [%1], 16, %2;"
        :: "r"(dst), "l"(src), "r"(sz) : "memory");
}
__device__ __forceinline__ void cp_commit() {
    asm volatile("cp.async.commit_group;" ::: "memory");
}
__device__ __forceinline__ void cp_wait0() {
    asm volatile("cp.async.wait_group 0;" ::: "memory");
}

// ================= fused logit GEMM =================
// mode 0, grid.x = 492: c0 tiles [0,157), c1 [157,314), c2 groups [314,439) x10,
//   c3 groups [439,492) x10. c0/c1: GEMM + raw store + sums. c2/c3: grouped GEMM,
//   sums only (A loaded once, B streamed, one reduction at end).
// mode 1, grid.x = 1780: c2 tiles [0,1250), c3 [1250,1780): recompute + adjusted store.
static constexpr int TILE_BUF = 128 * 144;
static constexpr int SM_LOG   = 4 * TILE_BUF;

__global__ void __launch_bounds__(256, 2)
logits_k(int mode,
         float* __restrict__ out,
         const float* __restrict__ bias0, const float* __restrict__ bias1,
         const float* __restrict__ bias2, const float* __restrict__ bias3,
         float* __restrict__ gsum,
         const float* __restrict__ clog,
         const float* __restrict__ lse)
{
    const int    ct_k[4]    = {1024, 256, 64, 16};
    const int    ct_aoff[4] = {0, 1024, 1280, 1344};
    const size_t ct_boff[4] = {B_W0, B_W1, B_W2, B_W3};
    const int    ct_n[4]    = {20000, 20000, 160000, 67735};
    const int    ct_col[4]  = {0, 20000, 40000, 200000};

    extern __shared__ __align__(16) char smem[];
    const uint32_t sb = smem_u32(smem);

    int c, tl0, G;
    if (mode == 0) {
        int t = blockIdx.x;
        if      (t < 157) { c = 0; tl0 = t;               G = 1;  }
        else if (t < 314) { c = 1; tl0 = t - 157;         G = 1;  }
        else if (t < 439) { c = 2; tl0 = (t - 314) * 10;  G = 10; }
        else              { c = 3; tl0 = (t - 439) * 10;  G = 10; }
    } else {
        int t = blockIdx.x;
        if (t < 1250) { c = 2; tl0 = t; }
        else          { c = 3; tl0 = t - 1250; }
        G = 1;
    }
    const int K  = ct_k[c];
    const int N  = ct_n[c];
    const int mt = blockIdx.y;
    const int kslim = (K >= 64) ? 4 : 1;
    const __nv_bfloat16* A = g_bf + B_Y + ct_aoff[c];
    const __nv_bfloat16* B = g_bf + ct_boff[c];
    const float* bias = (c == 0) ? bias0 : (c == 1) ? bias1 : (c == 2) ? bias2 : bias3;

    const int tid  = threadIdx.x;
    const int wid  = tid >> 5, lane = tid & 31;
    const int wm   = wid & 3;
    const int wn   = wid >> 2;
    const int g    = lane >> 2;
    const int tg   = lane & 3;
    const int lrow = tid >> 1;
    const int lseg = (tid & 1) * 4;

    if (mode == 0 && c >= 2) {
        // ============ PATH B: grouped, sums only ============
        // load A once (buffer 0)
        #pragma unroll
        for (int i = 0; i < 4; i++) {
            int kk = (lseg + i) * 8;
            cp16(sb + lrow * 144 + (lseg + i) * 16,
                 A + (size_t)(mt * 128 + lrow) * 1360 + kk, kk < K);
        }
        // B tile tl0 into buf2
        {
            int gn = tl0 * 128 + lrow;
            #pragma unroll
            for (int i = 0; i < 4; i++) {
                int kk = (lseg + i) * 8;
                cp16(sb + 2 * TILE_BUF + lrow * 144 + (lseg + i) * 16,
                     B + (size_t)(gn < N ? gn : 0) * K + kk, gn < N && kk < K);
            }
        }
        cp_commit();

        float rsum[2][2] = {{0.f, 0.f}, {0.f, 0.f}};

        for (int j = 0; j < G; j++) {
            const int tl = tl0 + j;
            const int n0 = tl * 128;
            const bool fullj = (n0 + 128 <= N);
            const int p = j & 1;
            cp_wait0();
            __syncthreads();

            if (j + 1 < G) {
                int gn = (tl + 1) * 128 + lrow;
                int q = p ^ 1;
                #pragma unroll
                for (int i = 0; i < 4; i++) {
                    int kk = (lseg + i) * 8;
                    cp16(sb + (2 + q) * TILE_BUF + lrow * 144 + (lseg + i) * 16,
                         B + (size_t)(gn < N ? gn : 0) * K + kk, gn < N && kk < K);
                }
                cp_commit();
            }

            float acc[2][8][4];
            #pragma unroll
            for (int mi = 0; mi < 2; mi++)
                #pragma unroll
                for (int ni = 0; ni < 8; ni++)
                    #pragma unroll
                    for (int q = 0; q < 4; q++) acc[mi][ni][q] = 0.0f;

            const uint32_t abase = sb;
            const uint32_t bbase = sb + (2 + p) * TILE_BUF;
            for (int ks = 0; ks < kslim; ks++) {
                const int kb = ks * 16;
                uint32_t afrag[2][4];
                #pragma unroll
                for (int mi = 0; mi < 2; mi++) {
                    int row = wm * 32 + mi * 16 + (lane & 15);
                    int col = kb + (lane >> 4) * 8;
                    ldsm_x4(afrag[mi][0], afrag[mi][1], afrag[mi][2], afrag[mi][3],
                            abase + row * 144 + col * 2);
                }
                #pragma unroll
                for (int nj = 0; nj < 4; nj++) {
                    int row = wn * 64 + nj * 16 + ((lane >> 4) << 3) + (lane & 7);
                    int col = kb + ((lane >> 3) & 1) * 8;
                    uint32_t b0, b1, b2, b3;
                    ldsm_x4(b0, b1, b2, b3, bbase + row * 144 + col * 2);
                    uint32_t be[2] = {b0, b1};
                    uint32_t bo[2] = {b2, b3};
                    #pragma unroll
                    for (int mi = 0; mi < 2; mi++) {
                        mma16816(acc[mi][2 * nj],     afrag[mi], be);
                        mma16816(acc[mi][2 * nj + 1], afrag[mi], bo);
                    }
                }
            }

            // bias + exp sums (accumulate into rsum across tiles)
            if (fullj) {
                #pragma unroll
                for (int ni = 0; ni < 8; ni++) {
                    float bv0 = bias[n0 + wn * 64 + ni * 8 + tg * 2];
                    float bv1 = bias[n0 + wn * 64 + ni * 8 + tg * 2 + 1];
                    #pragma unroll
                    for (int mi = 0; mi < 2; mi++) {
                        rsum[mi][0] += fast_exp(acc[mi][ni][0] + bv0)
                                     + fast_exp(acc[mi][ni][1] + bv1);
                        rsum[mi][1] += fast_exp(acc[mi][ni][2] + bv0)
                                     + fast_exp(acc[mi][ni][3] + bv1);
                    }
                }
            } else {
                #pragma unroll
                for (int ni = 0; ni < 8; ni++) {
                    int col = n0 + wn * 64 + ni * 8 + tg * 2;
                    if (col < N) {
                        float bv0 = bias[col];
                        #pragma unroll
                        for (int mi = 0; mi < 2; mi++) {
                            rsum[mi][0] += fast_exp(acc[mi][ni][0] + bv0);
                            rsum[mi][1] += fast_exp(acc[mi][ni][2] + bv0);
                        }
                    }
                    if (col + 1 < N) {
                        float bv1 = bias[col + 1];
                        #pragma unroll
                        for (int mi = 0; mi < 2; mi++) {
                            rsum[mi][0] += fast_exp(acc[mi][ni][1] + bv1);
                            rsum[mi][1] += fast_exp(acc[mi][ni][3] + bv1);
                        }
                    }
                }
            }
        }

        __syncthreads();
        float* saux = reinterpret_cast<float*>(smem);   // [256]
        #pragma unroll
        for (int mi = 0; mi < 2; mi++) {
            int rl = wm * 32 + mi * 16 + g;
            float s_lo = rsum[mi][0], s_hi = rsum[mi][1];
            s_lo += __shfl_xor_sync(0xffffffff, s_lo, 1);
            s_lo += __shfl_xor_sync(0xffffffff, s_lo, 2);
            s_hi += __shfl_xor_sync(0xffffffff, s_hi, 1);
            s_hi += __shfl_xor_sync(0xffffffff, s_hi, 2);
            if (tg == 0) {
                saux[rl * 2 + wn] = s_lo;
                saux[(rl + 8) * 2 + wn] = s_hi;
            }
        }
        __syncthreads();
        if (tid < 128) {
            float s = saux[tid * 2] + saux[tid * 2 + 1];
            atomicAdd(&gsum[(mt * 128 + tid) * 4 + c], s);
        }
        return;
    }

    // ============ PATH A: single tile ============
    const int tl = tl0;
    const int n0 = tl * 128;
    const bool full = (n0 + 128 <= N);
    const int nkc = (K + 63) >> 6;

    float acc[2][8][4];
    #pragma unroll
    for (int mi = 0; mi < 2; mi++)
        #pragma unroll
        for (int ni = 0; ni < 8; ni++)
            #pragma unroll
            for (int q = 0; q < 4; q++) acc[mi][ni][q] = 0.0f;

    {
        #pragma unroll
        for (int i = 0; i < 4; i++) {
            int kk = (lseg + i) * 8;
            cp16(sb + lrow * 144 + (lseg + i) * 16,
                 A + (size_t)(mt * 128 + lrow) * 1360 + kk, kk < K);
        }
        int gn = n0 + lrow;
        #pragma unroll
        for (int i = 0; i < 4; i++) {
            int kk = (lseg + i) * 8;
            cp16(sb + 2 * TILE_BUF + lrow * 144 + (lseg + i) * 16,
                 B + (size_t)(gn < N ? gn : 0) * K + kk, gn < N && kk < K);
        }
        cp_commit();
    }

    for (int kc = 0; kc < nkc; kc++) {
        const int p = kc & 1;
        cp_wait0();
        __syncthreads();

        if (kc + 1 < nkc) {
            const int k0 = (kc + 1) << 6;
            const int q = p ^ 1;
            #pragma unroll
            for (int i = 0; i < 4; i++) {
                int kk = k0 + (lseg + i) * 8;
                cp16(sb + q * TILE_BUF + lrow * 144 + (lseg + i) * 16,
                     A + (size_t)(mt * 128 + lrow) * 1360 + kk, kk < K);
            }
            int gn = n0 + lrow;
            #pragma unroll
            for (int i = 0; i < 4; i++) {
                int kk = k0 + (lseg + i) * 8;
                cp16(sb + (2 + q) * TILE_BUF + lrow * 144 + (lseg + i) * 16,
                     B + (size_t)(gn < N ? gn : 0) * K + kk, gn < N && kk < K);
            }
            cp_commit();
        }

        const uint32_t abase = sb + p * TILE_BUF;
        const uint32_t bbase = sb + (2 + p) * TILE_BUF;

        for (int ks = 0; ks < kslim; ks++) {
            const int kb = ks * 16;
            uint32_t afrag[2][4];
            #pragma unroll
            for (int mi = 0; mi < 2; mi++) {
                int row = wm * 32 + mi * 16 + (lane & 15);
                int col = kb + (lane >> 4) * 8;
                ldsm_x4(afrag[mi][0], afrag[mi][1], afrag[mi][2], afrag[mi][3],
                        abase + row * 144 + col * 2);
            }
            #pragma unroll
            for (int nj = 0; nj < 4; nj++) {
                int row = wn * 64 + nj * 16 + ((lane >> 4) << 3) + (lane & 7);
                int col = kb + ((lane >> 3) & 1) * 8;
                uint32_t b0, b1, b2, b3;
                ldsm_x4(b0, b1, b2, b3, bbase + row * 144 + col * 2);
                uint32_t be[2] = {b0, b1};
                uint32_t bo[2] = {b2, b3};
                #pragma unroll
                for (int mi = 0; mi < 2; mi++) {
                    mma16816(acc[mi][2 * nj],     afrag[mi], be);
                    mma16816(acc[mi][2 * nj + 1], afrag[mi], bo);
                }
            }
        }
        __syncthreads();
    }

    // bias fold
    if (full) {
        #pragma unroll
        for (int ni = 0; ni < 8; ni++) {
            #pragma unroll
            for (int q = 0; q < 2; q++) {
                float bvq = bias[n0 + wn * 64 + ni * 8 + tg * 2 + q];
                #pragma unroll
                for (int mi = 0; mi < 2; mi++) {
                    acc[mi][ni][q]     += bvq;
                    acc[mi][ni][q + 2] += bvq;
                }
            }
        }
    } else {
        #pragma unroll
        for (int ni = 0; ni < 8; ni++) {
            #pragma unroll
            for (int q = 0; q < 2; q++) {
                int col = n0 + wn * 64 + ni * 8 + tg * 2 + q;
                float bvq = (col < N) ? bias[col] : 0.0f;
                #pragma unroll
                for (int mi = 0; mi < 2; mi++) {
                    acc[mi][ni][q]     += bvq;
                    acc[mi][ni][q + 2] += bvq;
                }
            }
        }
    }

    float* stage = reinterpret_cast<float*>(smem);                 // [128][132]
    float* saux  = reinterpret_cast<float*>(smem) + 128 * 132;     // [256]

    if (mode == 0) {
        // c0/c1: exp sums + raw store
        #pragma unroll
        for (int mi = 0; mi < 2; mi++) {
            int rl = wm * 32 + mi * 16 + g;
            float s_lo = 0.0f, s_hi = 0.0f;
            if (full) {
                #pragma unroll
                for (int ni = 0; ni < 8; ni++) {
                    s_lo += fast_exp(acc[mi][ni][0]) + fast_exp(acc[mi][ni][1]);
                    s_hi += fast_exp(acc[mi][ni][2]) + fast_exp(acc[mi][ni][3]);
                }
            } else {
                #pragma unroll
                for (int ni = 0; ni < 8; ni++) {
                    int col = n0 + wn * 64 + ni * 8 + tg * 2;
                    if (col < N) {
                        s_lo += fast_exp(acc[mi][ni][0]);
                        s_hi += fast_exp(acc[mi][ni][2]);
                    }
                    if (col + 1 < N) {
                        s_lo += fast_exp(acc[mi][ni][1]);
                        s_hi += fast_exp(acc[mi][ni][3]);
                    }
                }
            }
            s_lo += __shfl_xor_sync(0xffffffff, s_lo, 1);
            s_lo += __shfl_xor_sync(0xffffffff, s_lo, 2);
            s_hi += __shfl_xor_sync(0xffffffff, s_hi, 1);
            s_hi += __shfl_xor_sync(0xffffffff, s_hi, 2);
            if (tg == 0) {
                saux[rl * 2 + wn] = s_lo;
                saux[(rl + 8) * 2 + wn] = s_hi;
            }
        }
        #pragma unroll
        for (int mi = 0; mi < 2; mi++) {
            int rl = wm * 32 + mi * 16 + g;
            #pragma unroll
            for (int ni = 0; ni < 8; ni++) {
                int cl = wn * 64 + ni * 8 + tg * 2;
                stage[rl * 132 + cl]           = acc[mi][ni][0];
                stage[rl * 132 + cl + 1]       = acc[mi][ni][1];
                stage[(rl + 8) * 132 + cl]     = acc[mi][ni][2];
                stage[(rl + 8) * 132 + cl + 1] = acc[mi][ni][3];
            }
        }
        __syncthreads();
        if (tid < 128) {
            float s = saux[tid * 2] + saux[tid * 2 + 1];
            atomicAdd(&gsum[(mt * 128 + tid) * 4 + c], s);
        }
        if (full) {
            #pragma unroll 4
            for (int it = 0; it < 64; it++) {
                int row = (it & 15) * 8 + wid;
                int col = (it >> 4) * 32 + lane;
                out[(size_t)(mt * 128 + row) * VOCAB + ct_col[c] + n0 + col] =
                    stage[row * 132 + col];
            }
        } else {
            #pragma unroll 4
            for (int it = 0; it < 64; it++) {
                int row = (it & 15) * 8 + wid;
                int col = (it >> 4) * 32 + lane;
                int gcol = n0 + col;
                if (gcol < N)
                    out[(size_t)(mt * 128 + row) * VOCAB + ct_col[c] + gcol] =
                        stage[row * 132 + col];
            }
        }
    } else {
        // pass 2: adjusted log-prob store (streaming)
        if (tid < 128) {
            int grow = mt * 128 + tid;
            float l0 = lse[grow * 4 + 0];
            saux[tid] = clog[grow * 3 + (c - 1)] - l0 - lse[grow * 4 + c];
        }
        #pragma unroll
        for (int mi = 0; mi < 2; mi++) {
            int rl = wm * 32 + mi * 16 + g;
            #pragma unroll
            for (int ni = 0; ni < 8; ni++) {
                int cl = wn * 64 + ni * 8 + tg * 2;
                stage[rl * 132 + cl]           = acc[mi][ni][0];
                stage[rl * 132 + cl + 1]       = acc[mi][ni][1];
                stage[(rl + 8) * 132 + cl]     = acc[mi][ni][2];
                stage[(rl + 8) * 132 + cl + 1] = acc[mi][ni][3];
            }
        }
        __syncthreads();
        if (full) {
            #pragma unroll 4
            for (int it = 0; it < 64; it++) {
                int row = (it & 15) * 8 + wid;
                int col = (it >> 4) * 32 + lane;
                float v = stage[row * 132 + col] + saux[row];
                __stcs(&out[(size_t)(mt * 128 + row) * VOCAB + ct_col[c] + n0 + col], v);
            }
        } else {
            #pragma unroll 4
            for (int it = 0; it < 64; it++) {
                int row = (it & 15) * 8 + wid;
                int col = (it >> 4) * 32 + lane;
                int gcol = n0 + col;
                if (gcol < N) {
                    float v = stage[row * 132 + col] + saux[row];
                    __stcs(&out[(size_t)(mt * 128 + row) * VOCAB + ct_col[c] + gcol], v);
                }
            }
        }
    }
}

// ================= projection GEMM (unchanged) =================
static constexpr int A_BUF_B = 128 * 144;
static constexpr int B_BUF_B = 256 * 144;
static constexpr int SM_GEMM = 2 * A_BUF_B + 2 * B_BUF_B;

__global__ void __launch_bounds__(256)
proj_gemm_k(const __nv_bfloat16* __restrict__ A, int lda,
            const __nv_bfloat16* __restrict__ B,
            int N, int K,
            __nv_bfloat16* __restrict__ Cb, int ldcb)
{
    extern __shared__ __align__(16) char smem[];
    const uint32_t sb = smem_u32(smem);
    const uint32_t sa_base = sb;
    const uint32_t sbb_base = sb + 2 * A_BUF_B;

    const int tid  = threadIdx.x;
    const int wid  = tid >> 5, lane = tid & 31;
    const int wm   = wid & 1;
    const int wn   = wid >> 1;
    const int g    = lane >> 2;
    const int tg   = lane & 3;
    const int mt   = blockIdx.y;
    const int n0   = blockIdx.x * 256;

    float acc[4][8][4];
    #pragma unroll
    for (int mi = 0; mi < 4; mi++)
        #pragma unroll
        for (int ni = 0; ni < 8; ni++)
            #pragma unroll
            for (int q = 0; q < 4; q++) acc[mi][ni][q] = 0.0f;

    const int arow = tid >> 3, aseg = tid & 7;
    const int nkc = (K + 63) >> 6;

    {
        #pragma unroll
        for (int i = 0; i < 4; i++) {
            int row = arow + i * 32;
            int kk = aseg * 8;
            cp16(sa_base + row * 144 + aseg * 16,
                 A + (size_t)(mt * 128 + row) * lda + kk, kk < K);
        }
        #pragma unroll
        for (int i = 0; i < 8; i++) {
            int row = arow + i * 32;
            int kk = aseg * 8;
            int gn = n0 + row;
            cp16(sbb_base + row * 144 + aseg * 16,
                 B + (size_t)(gn < N ? gn : 0) * K + kk, gn < N && kk < K);
        }
        cp_commit();
    }

    for (int kc = 0; kc < nkc; kc++) {
        const int p = kc & 1;
        cp_wait0();
        __syncthreads();

        if (kc + 1 < nkc) {
            const int k0 = (kc + 1) << 6;
            const int q = p ^ 1;
            #pragma unroll
            for (int i = 0; i < 4; i++) {
                int row = arow + i * 32;
                int kk = k0 + aseg * 8;
                cp16(sa_base + q * A_BUF_B + row * 144 + aseg * 16,
                     A + (size_t)(mt * 128 + row) * lda + kk, kk < K);
            }
            #pragma unroll
            for (int i = 0; i < 8; i++) {
                int row = arow + i * 32;
                int kk = k0 + aseg * 8;
                int gn = n0 + row;
                cp16(sbb_base + q * B_BUF_B + row * 144 + aseg * 16,
                     B + (size_t)(gn < N ? gn : 0) * K + kk, gn < N && kk < K);
            }
            cp_commit();
        }

        const uint32_t abase = sa_base + p * A_BUF_B;
        const uint32_t bbase = sbb_base + p * B_BUF_B;

        #pragma unroll
        for (int ks = 0; ks < 4; ks++) {
            const int kb = ks * 16;
            uint32_t afrag[4][4];
            #pragma unroll
            for (int mi = 0; mi < 4; mi++) {
                int row = wm * 64 + mi * 16 + (lane & 15);
                int col = kb + (lane >> 4) * 8;
                ldsm_x4(afrag[mi][0], afrag[mi][1], afrag[mi][2], afrag[mi][3],
                        abase + row * 144 + col * 2);
            }
            #pragma unroll
            for (int nj = 0; nj < 4; nj++) {
                int row = wn * 64 + nj * 16 + ((lane >> 4) << 3) + (lane & 7);
                int col = kb + ((lane >> 3) & 1) * 8;
                uint32_t b0, b1, b2, b3;
                ldsm_x4(b0, b1, b2, b3, bbase + row * 144 + col * 2);
                uint32_t be[2] = {b0, b1};
                uint32_t bo[2] = {b2, b3};
                #pragma unroll
                for (int mi = 0; mi < 4; mi++) {
                    mma16816(acc[mi][2 * nj],     afrag[mi], be);
                    mma16816(acc[mi][2 * nj + 1], afrag[mi], bo);
                }
            }
        }
        __syncthreads();
    }

    #pragma unroll
    for (int mi = 0; mi < 4; mi++) {
        int row = mt * 128 + wm * 64 + mi * 16 + g;
        #pragma unroll
        for (int ni = 0; ni < 8; ni++) {
            int col = n0 + wn * 64 + ni * 8 + tg * 2;
            __nv_bfloat162 v0 = __floats2bfloat162_rn(acc[mi][ni][0], acc[mi][ni][1]);
            __nv_bfloat162 v1 = __floats2bfloat162_rn(acc[mi][ni][2], acc[mi][ni][3]);
            if (col + 1 < N) {
                *reinterpret_cast<uint32_t*>(Cb + (size_t)row * ldcb + col) =
                    *reinterpret_cast<uint32_t*>(&v0);
                *reinterpret_cast<uint32_t*>(Cb + (size_t)(row + 8) * ldcb + col) =
                    *reinterpret_cast<uint32_t*>(&v1);
            } else if (col < N) {
                Cb[(size_t)row * ldcb + col] = __low2bfloat16(v0);
                Cb[(size_t)(row + 8) * ldcb + col] = __low2bfloat16(v1);
            }
        }
    }
}

// ---------------- cluster pseudo-token logits ----------------
__global__ void cluster_logits_k(const __nv_bfloat16* __restrict__ y0b, int ystride,
                                 const float* __restrict__ cw,
                                 const float* __restrict__ cb,
                                 float* __restrict__ clog)
{
    int r = blockIdx.x;
    int t = threadIdx.x;
    float s0 = 0.f, s1 = 0.f, s2 = 0.f;
    const __nv_bfloat16* yr = y0b + (size_t)r * ystride;
    for (int d = t; d < 1024; d += 128) {
        float yv = __bfloat162float(yr[d]);
        s0 += yv * cw[d];
        s1 += yv * cw[1024 + d];
        s2 += yv * cw[2048 + d];
    }
    __shared__ float sh[3][128];
    sh[0][t] = s0; sh[1][t] = s1; sh[2][t] = s2;
    __syncthreads();
    for (int off = 64; off > 0; off >>= 1) {
        if (t < off) {
            sh[0][t] += sh[0][t + off];
            sh[1][t] += sh[1][t + off];
            sh[2][t] += sh[2][t + off];
        }
        __syncthreads();
    }
    if (t < 3) clog[r * 3 + t] = sh[t][0] + cb[t];
}

// ---------------- finalize LSE ----------------
__global__ void lse_fin_k(const float* __restrict__ gsum,
                          const float* __restrict__ clog,
                          float* __restrict__ lse)
{
    int i = blockIdx.x * blockDim.x + threadIdx.x;
    if (i >= ROWS * 4) return;
    int r = i >> 2, c = i & 3;
    float s = gsum[i];
    if (c == 0)
        s += expf(clog[r * 3]) + expf(clog[r * 3 + 1]) + expf(clog[r * 3 + 2]);
    lse[i] = logf(s);
}

// ---------------- fixup clusters 0/1, scalar (VOCAB odd) ----------------
__global__ void fixup_k(float* __restrict__ out,
                        const float* __restrict__ clog,
                        const float* __restrict__ lse)
{
    int r = blockIdx.y;
    float l0 = lse[r * 4 + 0];
    float adj0 = -l0;
    float adj1 = clog[r * 3 + 0] - l0 - lse[r * 4 + 1];
    float* p = out + (size_t)r * VOCAB;
    int base = blockIdx.x * 10000;
    for (int col = base + threadIdx.x; col < base + 10000; col += blockDim.x) {
        float adj = (col < 20000) ? adj0 : adj1;
        p[col] += adj;
    }
}

// ---------------- loss ----------------
__global__ void loss_k(const float* __restrict__ out,
                       const int* __restrict__ target,
                       float* __restrict__ dst)
{
    int t = threadIdx.x;
    float v = out[(size_t)t * VOCAB + target[t]];
    __shared__ float sh[512];
    sh[t] = v;
    __syncthreads();
    for (int off = 256; off > 0; off >>= 1) {
        if (t < off) sh[t] += sh[t + off];
        __syncthreads();
    }
    if (t == 0) *dst = -sh[0] / 512.0f;
}

// ---------------- launcher ----------------
extern "C" void kernel_launch(void* const* d_in, const int* in_sizes, int n_in,
                              void* d_out, int out_size)
{
    const float *hidden = 0, *cw = 0, *cb = 0;
    const float *proj0 = 0, *proj1 = 0, *proj2 = 0, *proj3 = 0;
    const float *W0 = 0, *W1 = 0, *W2 = 0, *W3 = 0;
    const float *b0 = 0, *b1 = 0, *b2 = 0, *b3 = 0;
    const int *target = 0;

    for (int i = 0; i < n_in; i++) {
        const void* p = d_in[i];
        switch (in_sizes[i]) {
            case 524288:   hidden = (const float*)p; break;
            case 512:      target = (const int*)p;   break;
            case 3072:     cw = (const float*)p;     break;
            case 3:        cb = (const float*)p;     break;
            case 1048576:  proj0 = (const float*)p;  break;
            case 20480000: W0 = (const float*)p;     break;
            case 262144:   proj1 = (const float*)p;  break;
            case 5120000:  W1 = (const float*)p;     break;
            case 65536:    proj2 = (const float*)p;  break;
            case 10240000: W2 = (const float*)p;     break;
            case 160000:   b2 = (const float*)p;     break;
            case 16384:    proj3 = (const float*)p;  break;
            case 1083760:  W3 = (const float*)p;     break;
            case 67735:    b3 = (const float*)p;     break;
            case 20000:    if (!b0) b0 = (const float*)p; else b1 = (const float*)p; break;
            default: break;
        }
    }
    float* out = (float*)d_out;

    __nv_bfloat16* bf = nullptr;
    cudaGetSymbolAddress((void**)&bf, g_bf);
    float* f32s = nullptr;
    cudaGetSymbolAddress((void**)&f32s, g_f32);
    float* gsum = nullptr;
    cudaGetSymbolAddress((void**)&gsum, g_sum);
    float* clog = f32s;
    float* lse  = f32s + ROWS * 3;

    cudaFuncSetAttribute(proj_gemm_k, cudaFuncAttributeMaxDynamicSharedMemorySize, SM_GEMM);
    cudaFuncSetAttribute(logits_k, cudaFuncAttributeMaxDynamicSharedMemorySize, SM_LOG);

    conv_all_k<<<2368, 256>>>(W0, W1, W2, W3, proj0, proj1, proj2, proj3, hidden);

    proj_gemm_k<<<dim3(6, 4), 256, SM_GEMM>>>(bf + B_H, 1024, bf + B_P0, 1360, 1024,
        bf + B_Y, 1360);

    cluster_logits_k<<<ROWS, 128>>>(bf + B_Y, 1360, cw, cb, clog);

    // pass 1: c0/c1 raw store + sums; c2/c3 grouped sums only
    logits_k<<<dim3(492, 4), 256, SM_LOG>>>(0, out, b0, b1, b2, b3, gsum,
                                            nullptr, nullptr);
    lse_fin_k<<<2, 1024>>>(gsum, clog, lse);

    // pass 2: clusters 2/3 recompute + adjusted store
    logits_k<<<dim3(1780, 4), 256, SM_LOG>>>(1, out, b0, b1, b2, b3, nullptr,
                                             clog, lse);
    fixup_k<<<dim3(4, ROWS), 256>>>(out, clog, lse);

    long total = (long)ROWS * VOCAB;
    if ((long)out_size > total)
        loss_k<<<1, ROWS>>>(out, target, out + total);
}

// round 17
// speedup vs baseline: 1.3151x; 1.0748x over previous
#include <cuda_runtime.h>
#include <cuda_bf16.h>
#include <math.h>
#include <stdint.h>

static constexpr int VOCAB = 267735;
static constexpr int ROWS  = 512;

// bf16 scratch element offsets
static constexpr size_t B_W0 = 0;
static constexpr size_t B_W1 = 20480000;
static constexpr size_t B_W2 = 25600000;
static constexpr size_t B_W3 = 35840000;
static constexpr size_t B_P0 = 36923760;
static constexpr size_t B_H  = 38316400;
static constexpr size_t B_CONV_END = 38840688;
static constexpr size_t B_Y  = 38840688;
static constexpr size_t B_END = 38840688 + 512 * 1360;

__device__ __align__(16) __nv_bfloat16 g_bf[B_END];
__device__ __align__(16) float g_f32[ROWS * 3 + ROWS * 4];
__device__ __align__(16) float g_sum[ROWS * 4];

// ---------------- fast exp ----------------
__device__ __forceinline__ float fast_exp(float x) {
    float y = x * 1.4426950408889634f;
    float t = y + 12582912.0f;
    int   n = __float_as_int(t) - 0x4B400000;
    float f = y - (t - 12582912.0f);
    float u = f * 0.6931471805599453f;
    float p = 1.0f + u*(1.0f + u*(0.5f + u*(0.16666667f + u*0.041666667f)));
    return p * __int_as_float((n + 127) << 23);
}

// ---------------- fused convert + gsum zero ----------------
__global__ void conv_all_k(const float* __restrict__ w0, const float* __restrict__ w1,
                           const float* __restrict__ w2, const float* __restrict__ w3,
                           const float* __restrict__ p0, const float* __restrict__ p1,
                           const float* __restrict__ p2, const float* __restrict__ p3,
                           const float* __restrict__ hh)
{
    int gi = blockIdx.x * blockDim.x + threadIdx.x;
    if (gi < ROWS * 4) g_sum[gi] = 0.0f;

    const size_t e1 = 20480000, e2 = 25600000, e3 = 35840000, e4 = 36923760;
    const size_t e5 = 37972336, e6 = 38234480, e7 = 38300016, e8 = 38316400;
    const size_t nchunks = B_CONV_END / 8;
    size_t stride = (size_t)gridDim.x * blockDim.x;
    for (size_t c = (size_t)gi; c < nchunks; c += stride) {
        size_t e = c * 8;
        const float* src;
        size_t base;
        if      (e < e1) { src = w0; base = 0;  }
        else if (e < e2) { src = w1; base = e1; }
        else if (e < e3) { src = w2; base = e2; }
        else if (e < e4) { src = w3; base = e3; }
        else if (e < e5) { src = p0; base = e4; }
        else if (e < e6) { src = p1; base = e5; }
        else if (e < e7) { src = p2; base = e6; }
        else if (e < e8) { src = p3; base = e7; }
        else             { src = hh; base = e8; }
        const float4* s = reinterpret_cast<const float4*>(src + (e - base));
        float4 v0 = s[0];
        float4 v1 = s[1];
        __nv_bfloat162 a0 = __floats2bfloat162_rn(v0.x, v0.y);
        __nv_bfloat162 a1 = __floats2bfloat162_rn(v0.z, v0.w);
        __nv_bfloat162 a2 = __floats2bfloat162_rn(v1.x, v1.y);
        __nv_bfloat162 a3 = __floats2bfloat162_rn(v1.z, v1.w);
        uint4 u;
        u.x = *reinterpret_cast<uint32_t*>(&a0);
        u.y = *reinterpret_cast<uint32_t*>(&a1);
        u.z = *reinterpret_cast<uint32_t*>(&a2);
        u.w = *reinterpret_cast<uint32_t*>(&a3);
        *reinterpret_cast<uint4*>(g_bf + e) = u;
    }
}

// ---------------- PTX helpers ----------------
__device__ __forceinline__ uint32_t smem_u32(const void* p) {
    uint32_t a;
    asm("{ .reg .u64 t; cvta.to.shared.u64 t, %1; cvt.u32.u64 %0, t; }" : "=r"(a) : "l"(p));
    return a;
}
__device__ __forceinline__ void mma16816(float* c, const uint32_t* a, const uint32_t* b) {
    asm volatile(
        "mma.sync.aligned.m16n8k16.row.col.f32.bf16.bf16.f32 "
        "{%0,%1,%2,%3}, {%4,%5,%6,%7}, {%8,%9}, {%0,%1,%2,%3};"
        : "+f"(c[0]), "+f"(c[1]), "+f"(c[2]), "+f"(c[3])
        : "r"(a[0]), "r"(a[1]), "r"(a[2]), "r"(a[3]), "r"(b[0]), "r"(b[1]));
}
__device__ __forceinline__ void ldsm_x4(uint32_t& r0, uint32_t& r1, uint32_t& r2, uint32_t& r3,
                                        uint32_t addr) {
    asm volatile("ldmatrix.sync.aligned.m8n8.x4.shared.b16 {%0,%1,%2,%3}, [%4];"
        : "=r"(r0), "=r"(r1), "=r"(r2), "=r"(r3) : "r"(addr));
}
__device__ __forceinline__ void cp16(uint32_t dst, const void* src, bool valid) {
    int sz = valid ? 16 : 0;
    asm volatile("cp.async.cg.shared.global [%0], [%1], 16, %2;"
        :: "r"(dst), "l"(src), "r"(sz) : "memory");
}
__device__ __forceinline__ void cp_commit() {
    asm volatile("cp.async.commit_group;" ::: "memory");
}
__device__ __forceinline__ void cp_wait0() {
    asm volatile("cp.async.wait_group 0;" ::: "memory");
}

// ================= fused logit GEMM =================
// mode 0, grid.x = 492: c0 [0,157), c1 [157,314): GEMM + raw store + sums.
//   c2 groups [314,439)x10, c3 groups [439,492)x10: grouped GEMM, sums only.
// mode 1, grid.x = 178: c2 groups [0,125)x10, c3 groups [125,178)x10:
//   grouped recompute + adjusted half-staged store.
static constexpr int TILE_BUF = 128 * 144;      // 18432
static constexpr int SM_LOG   = 4 * TILE_BUF;   // 73728 (mode 0)
static constexpr int STAGE64  = 64 * 132 * 4;   // 33792
static constexpr int SM_LOG2  = 3 * TILE_BUF + STAGE64 + 512;  // 89600 (mode 1)

__global__ void __launch_bounds__(256, 2)
logits_k(int mode,
         float* __restrict__ out,
         const float* __restrict__ bias0, const float* __restrict__ bias1,
         const float* __restrict__ bias2, const float* __restrict__ bias3,
         float* __restrict__ gsum,
         const float* __restrict__ clog,
         const float* __restrict__ lse)
{
    const int    ct_k[4]    = {1024, 256, 64, 16};
    const int    ct_aoff[4] = {0, 1024, 1280, 1344};
    const size_t ct_boff[4] = {B_W0, B_W1, B_W2, B_W3};
    const int    ct_n[4]    = {20000, 20000, 160000, 67735};
    const int    ct_col[4]  = {0, 20000, 40000, 200000};

    extern __shared__ __align__(16) char smem[];
    const uint32_t sb = smem_u32(smem);

    int c, tl0, G;
    if (mode == 0) {
        int t = blockIdx.x;
        if      (t < 157) { c = 0; tl0 = t;               G = 1;  }
        else if (t < 314) { c = 1; tl0 = t - 157;         G = 1;  }
        else if (t < 439) { c = 2; tl0 = (t - 314) * 10;  G = 10; }
        else              { c = 3; tl0 = (t - 439) * 10;  G = 10; }
    } else {
        int t = blockIdx.x;
        if (t < 125) { c = 2; tl0 = t * 10; }
        else         { c = 3; tl0 = (t - 125) * 10; }
        G = 10;
    }
    const int K  = ct_k[c];
    const int N  = ct_n[c];
    const int mt = blockIdx.y;
    const int kslim = (K >= 64) ? 4 : 1;
    const __nv_bfloat16* A = g_bf + B_Y + ct_aoff[c];
    const __nv_bfloat16* B = g_bf + ct_boff[c];
    const float* bias = (c == 0) ? bias0 : (c == 1) ? bias1 : (c == 2) ? bias2 : bias3;

    const int tid  = threadIdx.x;
    const int wid  = tid >> 5, lane = tid & 31;
    const int wm   = wid & 3;
    const int wn   = wid >> 2;
    const int g    = lane >> 2;
    const int tg   = lane & 3;
    const int lrow = tid >> 1;
    const int lseg = (tid & 1) * 4;

    if (mode == 1) {
        // ============ grouped recompute + adjusted store ============
        float* stage = reinterpret_cast<float*>(smem + 3 * TILE_BUF);       // [64][132]
        float* sadj  = reinterpret_cast<float*>(smem + 3 * TILE_BUF + STAGE64); // [128]
        if (tid < 128) {
            int grow = mt * 128 + tid;
            float l0 = lse[grow * 4 + 0];
            sadj[tid] = clog[grow * 3 + (c - 1)] - l0 - lse[grow * 4 + c];
        }
        // load A once (buf at sb)
        #pragma unroll
        for (int i = 0; i < 4; i++) {
            int kk = (lseg + i) * 8;
            cp16(sb + lrow * 144 + (lseg + i) * 16,
                 A + (size_t)(mt * 128 + lrow) * 1360 + kk, kk < K);
        }
        // first B tile into Bbuf0 (sb + TILE_BUF)
        {
            int gn = tl0 * 128 + lrow;
            #pragma unroll
            for (int i = 0; i < 4; i++) {
                int kk = (lseg + i) * 8;
                cp16(sb + TILE_BUF + lrow * 144 + (lseg + i) * 16,
                     B + (size_t)(gn < N ? gn : 0) * K + kk, gn < N && kk < K);
            }
        }
        cp_commit();

        for (int j = 0; j < G; j++) {
            const int tl = tl0 + j;
            const int n0 = tl * 128;
            const bool fullj = (n0 + 128 <= N);
            const int p = j & 1;
            cp_wait0();
            __syncthreads();

            if (j + 1 < G) {
                int gn = (tl + 1) * 128 + lrow;
                int q = p ^ 1;
                #pragma unroll
                for (int i = 0; i < 4; i++) {
                    int kk = (lseg + i) * 8;
                    cp16(sb + (1 + q) * TILE_BUF + lrow * 144 + (lseg + i) * 16,
                         B + (size_t)(gn < N ? gn : 0) * K + kk, gn < N && kk < K);
                }
                cp_commit();
            }

            float acc[2][8][4];
            #pragma unroll
            for (int mi = 0; mi < 2; mi++)
                #pragma unroll
                for (int ni = 0; ni < 8; ni++)
                    #pragma unroll
                    for (int q = 0; q < 4; q++) acc[mi][ni][q] = 0.0f;

            const uint32_t abase = sb;
            const uint32_t bbase = sb + (1 + p) * TILE_BUF;
            for (int ks = 0; ks < kslim; ks++) {
                const int kb = ks * 16;
                uint32_t afrag[2][4];
                #pragma unroll
                for (int mi = 0; mi < 2; mi++) {
                    int row = wm * 32 + mi * 16 + (lane & 15);
                    int col = kb + (lane >> 4) * 8;
                    ldsm_x4(afrag[mi][0], afrag[mi][1], afrag[mi][2], afrag[mi][3],
                            abase + row * 144 + col * 2);
                }
                #pragma unroll
                for (int nj = 0; nj < 4; nj++) {
                    int row = wn * 64 + nj * 16 + ((lane >> 4) << 3) + (lane & 7);
                    int col = kb + ((lane >> 3) & 1) * 8;
                    uint32_t b0, b1, b2, b3;
                    ldsm_x4(b0, b1, b2, b3, bbase + row * 144 + col * 2);
                    uint32_t be[2] = {b0, b1};
                    uint32_t bo[2] = {b2, b3};
                    #pragma unroll
                    for (int mi = 0; mi < 2; mi++) {
                        mma16816(acc[mi][2 * nj],     afrag[mi], be);
                        mma16816(acc[mi][2 * nj + 1], afrag[mi], bo);
                    }
                }
            }

            // bias + adj fold
            #pragma unroll
            for (int ni = 0; ni < 8; ni++) {
                #pragma unroll
                for (int q = 0; q < 2; q++) {
                    int col = n0 + wn * 64 + ni * 8 + tg * 2 + q;
                    float bvq = (col < N) ? bias[col] : 0.0f;
                    #pragma unroll
                    for (int mi = 0; mi < 2; mi++) {
                        acc[mi][ni][q]     += bvq;
                        acc[mi][ni][q + 2] += bvq;
                    }
                }
            }

            // two half-stages of 64 rows each
            #pragma unroll
            for (int h = 0; h < 2; h++) {
                if ((wm >> 1) == h) {
                    #pragma unroll
                    for (int mi = 0; mi < 2; mi++) {
                        int rl = (wm & 1) * 32 + mi * 16 + g;   // 0..63 local
                        int grow = mt * 128 + h * 64 + rl;
                        float a0 = sadj[h * 64 + rl];
                        float a1 = sadj[h * 64 + rl + 8];
                        (void)grow;
                        #pragma unroll
                        for (int ni = 0; ni < 8; ni++) {
                            int cl = wn * 64 + ni * 8 + tg * 2;
                            stage[rl * 132 + cl]           = acc[mi][ni][0] + a0;
                            stage[rl * 132 + cl + 1]       = acc[mi][ni][1] + a0;
                            stage[(rl + 8) * 132 + cl]     = acc[mi][ni][2] + a1;
                            stage[(rl + 8) * 132 + cl + 1] = acc[mi][ni][3] + a1;
                        }
                    }
                }
                __syncthreads();
                if (fullj) {
                    #pragma unroll 4
                    for (int it = 0; it < 32; it++) {
                        int row = (it & 7) * 8 + wid;
                        int col = (it >> 3) * 32 + lane;
                        __stcs(&out[(size_t)(mt * 128 + h * 64 + row) * VOCAB
                                    + ct_col[c] + n0 + col],
                               stage[row * 132 + col]);
                    }
                } else {
                    #pragma unroll 4
                    for (int it = 0; it < 32; it++) {
                        int row = (it & 7) * 8 + wid;
                        int col = (it >> 3) * 32 + lane;
                        int gcol = n0 + col;
                        if (gcol < N)
                            __stcs(&out[(size_t)(mt * 128 + h * 64 + row) * VOCAB
                                        + ct_col[c] + gcol],
                                   stage[row * 132 + col]);
                    }
                }
                __syncthreads();
            }
        }
        return;
    }

    if (c >= 2) {
        // ============ mode 0 grouped: sums only ============
        #pragma unroll
        for (int i = 0; i < 4; i++) {
            int kk = (lseg + i) * 8;
            cp16(sb + lrow * 144 + (lseg + i) * 16,
                 A + (size_t)(mt * 128 + lrow) * 1360 + kk, kk < K);
        }
        {
            int gn = tl0 * 128 + lrow;
            #pragma unroll
            for (int i = 0; i < 4; i++) {
                int kk = (lseg + i) * 8;
                cp16(sb + 2 * TILE_BUF + lrow * 144 + (lseg + i) * 16,
                     B + (size_t)(gn < N ? gn : 0) * K + kk, gn < N && kk < K);
            }
        }
        cp_commit();

        float rsum[2][2] = {{0.f, 0.f}, {0.f, 0.f}};

        for (int j = 0; j < G; j++) {
            const int tl = tl0 + j;
            const int n0 = tl * 128;
            const bool fullj = (n0 + 128 <= N);
            const int p = j & 1;
            cp_wait0();
            __syncthreads();

            if (j + 1 < G) {
                int gn = (tl + 1) * 128 + lrow;
                int q = p ^ 1;
                #pragma unroll
                for (int i = 0; i < 4; i++) {
                    int kk = (lseg + i) * 8;
                    cp16(sb + (2 + q) * TILE_BUF + lrow * 144 + (lseg + i) * 16,
                         B + (size_t)(gn < N ? gn : 0) * K + kk, gn < N && kk < K);
                }
                cp_commit();
            }

            float acc[2][8][4];
            #pragma unroll
            for (int mi = 0; mi < 2; mi++)
                #pragma unroll
                for (int ni = 0; ni < 8; ni++)
                    #pragma unroll
                    for (int q = 0; q < 4; q++) acc[mi][ni][q] = 0.0f;

            const uint32_t abase = sb;
            const uint32_t bbase = sb + (2 + p) * TILE_BUF;
            for (int ks = 0; ks < kslim; ks++) {
                const int kb = ks * 16;
                uint32_t afrag[2][4];
                #pragma unroll
                for (int mi = 0; mi < 2; mi++) {
                    int row = wm * 32 + mi * 16 + (lane & 15);
                    int col = kb + (lane >> 4) * 8;
                    ldsm_x4(afrag[mi][0], afrag[mi][1], afrag[mi][2], afrag[mi][3],
                            abase + row * 144 + col * 2);
                }
                #pragma unroll
                for (int nj = 0; nj < 4; nj++) {
                    int row = wn * 64 + nj * 16 + ((lane >> 4) << 3) + (lane & 7);
                    int col = kb + ((lane >> 3) & 1) * 8;
                    uint32_t b0, b1, b2, b3;
                    ldsm_x4(b0, b1, b2, b3, bbase + row * 144 + col * 2);
                    uint32_t be[2] = {b0, b1};
                    uint32_t bo[2] = {b2, b3};
                    #pragma unroll
                    for (int mi = 0; mi < 2; mi++) {
                        mma16816(acc[mi][2 * nj],     afrag[mi], be);
                        mma16816(acc[mi][2 * nj + 1], afrag[mi], bo);
                    }
                }
            }

            if (fullj) {
                #pragma unroll
                for (int ni = 0; ni < 8; ni++) {
                    float bv0 = bias[n0 + wn * 64 + ni * 8 + tg * 2];
                    float bv1 = bias[n0 + wn * 64 + ni * 8 + tg * 2 + 1];
                    #pragma unroll
                    for (int mi = 0; mi < 2; mi++) {
                        rsum[mi][0] += fast_exp(acc[mi][ni][0] + bv0)
                                     + fast_exp(acc[mi][ni][1] + bv1);
                        rsum[mi][1] += fast_exp(acc[mi][ni][2] + bv0)
                                     + fast_exp(acc[mi][ni][3] + bv1);
                    }
                }
            } else {
                #pragma unroll
                for (int ni = 0; ni < 8; ni++) {
                    int col = n0 + wn * 64 + ni * 8 + tg * 2;
                    if (col < N) {
                        float bv0 = bias[col];
                        #pragma unroll
                        for (int mi = 0; mi < 2; mi++) {
                            rsum[mi][0] += fast_exp(acc[mi][ni][0] + bv0);
                            rsum[mi][1] += fast_exp(acc[mi][ni][2] + bv0);
                        }
                    }
                    if (col + 1 < N) {
                        float bv1 = bias[col + 1];
                        #pragma unroll
                        for (int mi = 0; mi < 2; mi++) {
                            rsum[mi][0] += fast_exp(acc[mi][ni][1] + bv1);
                            rsum[mi][1] += fast_exp(acc[mi][ni][3] + bv1);
                        }
                    }
                }
            }
        }

        __syncthreads();
        float* saux = reinterpret_cast<float*>(smem);
        #pragma unroll
        for (int mi = 0; mi < 2; mi++) {
            int rl = wm * 32 + mi * 16 + g;
            float s_lo = rsum[mi][0], s_hi = rsum[mi][1];
            s_lo += __shfl_xor_sync(0xffffffff, s_lo, 1);
            s_lo += __shfl_xor_sync(0xffffffff, s_lo, 2);
            s_hi += __shfl_xor_sync(0xffffffff, s_hi, 1);
            s_hi += __shfl_xor_sync(0xffffffff, s_hi, 2);
            if (tg == 0) {
                saux[rl * 2 + wn] = s_lo;
                saux[(rl + 8) * 2 + wn] = s_hi;
            }
        }
        __syncthreads();
        if (tid < 128) {
            float s = saux[tid * 2] + saux[tid * 2 + 1];
            atomicAdd(&gsum[(mt * 128 + tid) * 4 + c], s);
        }
        return;
    }

    // ============ mode 0, c0/c1: single tile, raw store + sums ============
    const int tl = tl0;
    const int n0 = tl * 128;
    const bool full = (n0 + 128 <= N);
    const int nkc = (K + 63) >> 6;

    float acc[2][8][4];
    #pragma unroll
    for (int mi = 0; mi < 2; mi++)
        #pragma unroll
        for (int ni = 0; ni < 8; ni++)
            #pragma unroll
            for (int q = 0; q < 4; q++) acc[mi][ni][q] = 0.0f;

    {
        #pragma unroll
        for (int i = 0; i < 4; i++) {
            int kk = (lseg + i) * 8;
            cp16(sb + lrow * 144 + (lseg + i) * 16,
                 A + (size_t)(mt * 128 + lrow) * 1360 + kk, kk < K);
        }
        int gn = n0 + lrow;
        #pragma unroll
        for (int i = 0; i < 4; i++) {
            int kk = (lseg + i) * 8;
            cp16(sb + 2 * TILE_BUF + lrow * 144 + (lseg + i) * 16,
                 B + (size_t)(gn < N ? gn : 0) * K + kk, gn < N && kk < K);
        }
        cp_commit();
    }

    for (int kc = 0; kc < nkc; kc++) {
        const int p = kc & 1;
        cp_wait0();
        __syncthreads();

        if (kc + 1 < nkc) {
            const int k0 = (kc + 1) << 6;
            const int q = p ^ 1;
            #pragma unroll
            for (int i = 0; i < 4; i++) {
                int kk = k0 + (lseg + i) * 8;
                cp16(sb + q * TILE_BUF + lrow * 144 + (lseg + i) * 16,
                     A + (size_t)(mt * 128 + lrow) * 1360 + kk, kk < K);
            }
            int gn = n0 + lrow;
            #pragma unroll
            for (int i = 0; i < 4; i++) {
                int kk = k0 + (lseg + i) * 8;
                cp16(sb + (2 + q) * TILE_BUF + lrow * 144 + (lseg + i) * 16,
                     B + (size_t)(gn < N ? gn : 0) * K + kk, gn < N && kk < K);
            }
            cp_commit();
        }

        const uint32_t abase = sb + p * TILE_BUF;
        const uint32_t bbase = sb + (2 + p) * TILE_BUF;

        #pragma unroll
        for (int ks = 0; ks < 4; ks++) {
            const int kb = ks * 16;
            uint32_t afrag[2][4];
            #pragma unroll
            for (int mi = 0; mi < 2; mi++) {
                int row = wm * 32 + mi * 16 + (lane & 15);
                int col = kb + (lane >> 4) * 8;
                ldsm_x4(afrag[mi][0], afrag[mi][1], afrag[mi][2], afrag[mi][3],
                        abase + row * 144 + col * 2);
            }
            #pragma unroll
            for (int nj = 0; nj < 4; nj++) {
                int row = wn * 64 + nj * 16 + ((lane >> 4) << 3) + (lane & 7);
                int col = kb + ((lane >> 3) & 1) * 8;
                uint32_t b0, b1, b2, b3;
                ldsm_x4(b0, b1, b2, b3, bbase + row * 144 + col * 2);
                uint32_t be[2] = {b0, b1};
                uint32_t bo[2] = {b2, b3};
                #pragma unroll
                for (int mi = 0; mi < 2; mi++) {
                    mma16816(acc[mi][2 * nj],     afrag[mi], be);
                    mma16816(acc[mi][2 * nj + 1], afrag[mi], bo);
                }
            }
        }
        __syncthreads();
    }

    if (full) {
        #pragma unroll
        for (int ni = 0; ni < 8; ni++) {
            #pragma unroll
            for (int q = 0; q < 2; q++) {
                float bvq = bias[n0 + wn * 64 + ni * 8 + tg * 2 + q];
                #pragma unroll
                for (int mi = 0; mi < 2; mi++) {
                    acc[mi][ni][q]     += bvq;
                    acc[mi][ni][q + 2] += bvq;
                }
            }
        }
    } else {
        #pragma unroll
        for (int ni = 0; ni < 8; ni++) {
            #pragma unroll
            for (int q = 0; q < 2; q++) {
                int col = n0 + wn * 64 + ni * 8 + tg * 2 + q;
                float bvq = (col < N) ? bias[col] : 0.0f;
                #pragma unroll
                for (int mi = 0; mi < 2; mi++) {
                    acc[mi][ni][q]     += bvq;
                    acc[mi][ni][q + 2] += bvq;
                }
            }
        }
    }

    float* stage = reinterpret_cast<float*>(smem);                 // [128][132]
    float* saux  = reinterpret_cast<float*>(smem) + 128 * 132;     // [256]

    #pragma unroll
    for (int mi = 0; mi < 2; mi++) {
        int rl = wm * 32 + mi * 16 + g;
        float s_lo = 0.0f, s_hi = 0.0f;
        if (full) {
            #pragma unroll
            for (int ni = 0; ni < 8; ni++) {
                s_lo += fast_exp(acc[mi][ni][0]) + fast_exp(acc[mi][ni][1]);
                s_hi += fast_exp(acc[mi][ni][2]) + fast_exp(acc[mi][ni][3]);
            }
        } else {
            #pragma unroll
            for (int ni = 0; ni < 8; ni++) {
                int col = n0 + wn * 64 + ni * 8 + tg * 2;
                if (col < N) {
                    s_lo += fast_exp(acc[mi][ni][0]);
                    s_hi += fast_exp(acc[mi][ni][2]);
                }
                if (col + 1 < N) {
                    s_lo += fast_exp(acc[mi][ni][1]);
                    s_hi += fast_exp(acc[mi][ni][3]);
                }
            }
        }
        s_lo += __shfl_xor_sync(0xffffffff, s_lo, 1);
        s_lo += __shfl_xor_sync(0xffffffff, s_lo, 2);
        s_hi += __shfl_xor_sync(0xffffffff, s_hi, 1);
        s_hi += __shfl_xor_sync(0xffffffff, s_hi, 2);
        if (tg == 0) {
            saux[rl * 2 + wn] = s_lo;
            saux[(rl + 8) * 2 + wn] = s_hi;
        }
    }
    #pragma unroll
    for (int mi = 0; mi < 2; mi++) {
        int rl = wm * 32 + mi * 16 + g;
        #pragma unroll
        for (int ni = 0; ni < 8; ni++) {
            int cl = wn * 64 + ni * 8 + tg * 2;
            stage[rl * 132 + cl]           = acc[mi][ni][0];
            stage[rl * 132 + cl + 1]       = acc[mi][ni][1];
            stage[(rl + 8) * 132 + cl]     = acc[mi][ni][2];
            stage[(rl + 8) * 132 + cl + 1] = acc[mi][ni][3];
        }
    }
    __syncthreads();
    if (tid < 128) {
        float s = saux[tid * 2] + saux[tid * 2 + 1];
        atomicAdd(&gsum[(mt * 128 + tid) * 4 + c], s);
    }
    if (full) {
        #pragma unroll 4
        for (int it = 0; it < 64; it++) {
            int row = (it & 15) * 8 + wid;
            int col = (it >> 4) * 32 + lane;
            out[(size_t)(mt * 128 + row) * VOCAB + ct_col[c] + n0 + col] =
                stage[row * 132 + col];
        }
    } else {
        #pragma unroll 4
        for (int it = 0; it < 64; it++) {
            int row = (it & 15) * 8 + wid;
            int col = (it >> 4) * 32 + lane;
            int gcol = n0 + col;
            if (gcol < N)
                out[(size_t)(mt * 128 + row) * VOCAB + ct_col[c] + gcol] =
                    stage[row * 132 + col];
        }
    }
}

// ================= projection GEMM (unchanged) =================
static constexpr int A_BUF_B = 128 * 144;
static constexpr int B_BUF_B = 256 * 144;
static constexpr int SM_GEMM = 2 * A_BUF_B + 2 * B_BUF_B;

__global__ void __launch_bounds__(256)
proj_gemm_k(const __nv_bfloat16* __restrict__ A, int lda,
            const __nv_bfloat16* __restrict__ B,
            int N, int K,
            __nv_bfloat16* __restrict__ Cb, int ldcb)
{
    extern __shared__ __align__(16) char smem[];
    const uint32_t sb = smem_u32(smem);
    const uint32_t sa_base = sb;
    const uint32_t sbb_base = sb + 2 * A_BUF_B;

    const int tid  = threadIdx.x;
    const int wid  = tid >> 5, lane = tid & 31;
    const int wm   = wid & 1;
    const int wn   = wid >> 1;
    const int g    = lane >> 2;
    const int tg   = lane & 3;
    const int mt   = blockIdx.y;
    const int n0   = blockIdx.x * 256;

    float acc[4][8][4];
    #pragma unroll
    for (int mi = 0; mi < 4; mi++)
        #pragma unroll
        for (int ni = 0; ni < 8; ni++)
            #pragma unroll
            for (int q = 0; q < 4; q++) acc[mi][ni][q] = 0.0f;

    const int arow = tid >> 3, aseg = tid & 7;
    const int nkc = (K + 63) >> 6;

    {
        #pragma unroll
        for (int i = 0; i < 4; i++) {
            int row = arow + i * 32;
            int kk = aseg * 8;
            cp16(sa_base + row * 144 + aseg * 16,
                 A + (size_t)(mt * 128 + row) * lda + kk, kk < K);
        }
        #pragma unroll
        for (int i = 0; i < 8; i++) {
            int row = arow + i * 32;
            int kk = aseg * 8;
            int gn = n0 + row;
            cp16(sbb_base + row * 144 + aseg * 16,
                 B + (size_t)(gn < N ? gn : 0) * K + kk, gn < N && kk < K);
        }
        cp_commit();
    }

    for (int kc = 0; kc < nkc; kc++) {
        const int p = kc & 1;
        cp_wait0();
        __syncthreads();

        if (kc + 1 < nkc) {
            const int k0 = (kc + 1) << 6;
            const int q = p ^ 1;
            #pragma unroll
            for (int i = 0; i < 4; i++) {
                int row = arow + i * 32;
                int kk = k0 + aseg * 8;
                cp16(sa_base + q * A_BUF_B + row * 144 + aseg * 16,
                     A + (size_t)(mt * 128 + row) * lda + kk, kk < K);
            }
            #pragma unroll
            for (int i = 0; i < 8; i++) {
                int row = arow + i * 32;
                int kk = k0 + aseg * 8;
                int gn = n0 + row;
                cp16(sbb_base + q * B_BUF_B + row * 144 + aseg * 16,
                     B + (size_t)(gn < N ? gn : 0) * K + kk, gn < N && kk < K);
            }
            cp_commit();
        }

        const uint32_t abase = sa_base + p * A_BUF_B;
        const uint32_t bbase = sbb_base + p * B_BUF_B;

        #pragma unroll
        for (int ks = 0; ks < 4; ks++) {
            const int kb = ks * 16;
            uint32_t afrag[4][4];
            #pragma unroll
            for (int mi = 0; mi < 4; mi++) {
                int row = wm * 64 + mi * 16 + (lane & 15);
                int col = kb + (lane >> 4) * 8;
                ldsm_x4(afrag[mi][0], afrag[mi][1], afrag[mi][2], afrag[mi][3],
                        abase + row * 144 + col * 2);
            }
            #pragma unroll
            for (int nj = 0; nj < 4; nj++) {
                int row = wn * 64 + nj * 16 + ((lane >> 4) << 3) + (lane & 7);
                int col = kb + ((lane >> 3) & 1) * 8;
                uint32_t b0, b1, b2, b3;
                ldsm_x4(b0, b1, b2, b3, bbase + row * 144 + col * 2);
                uint32_t be[2] = {b0, b1};
                uint32_t bo[2] = {b2, b3};
                #pragma unroll
                for (int mi = 0; mi < 4; mi++) {
                    mma16816(acc[mi][2 * nj],     afrag[mi], be);
                    mma16816(acc[mi][2 * nj + 1], afrag[mi], bo);
                }
            }
        }
        __syncthreads();
    }

    #pragma unroll
    for (int mi = 0; mi < 4; mi++) {
        int row = mt * 128 + wm * 64 + mi * 16 + g;
        #pragma unroll
        for (int ni = 0; ni < 8; ni++) {
            int col = n0 + wn * 64 + ni * 8 + tg * 2;
            __nv_bfloat162 v0 = __floats2bfloat162_rn(acc[mi][ni][0], acc[mi][ni][1]);
            __nv_bfloat162 v1 = __floats2bfloat162_rn(acc[mi][ni][2], acc[mi][ni][3]);
            if (col + 1 < N) {
                *reinterpret_cast<uint32_t*>(Cb + (size_t)row * ldcb + col) =
                    *reinterpret_cast<uint32_t*>(&v0);
                *reinterpret_cast<uint32_t*>(Cb + (size_t)(row + 8) * ldcb + col) =
                    *reinterpret_cast<uint32_t*>(&v1);
            } else if (col < N) {
                Cb[(size_t)row * ldcb + col] = __low2bfloat16(v0);
                Cb[(size_t)(row + 8) * ldcb + col] = __low2bfloat16(v1);
            }
        }
    }
}

// ---------------- cluster pseudo-token logits ----------------
__global__ void cluster_logits_k(const __nv_bfloat16* __restrict__ y0b, int ystride,
                                 const float* __restrict__ cw,
                                 const float* __restrict__ cb,
                                 float* __restrict__ clog)
{
    int r = blockIdx.x;
    int t = threadIdx.x;
    float s0 = 0.f, s1 = 0.f, s2 = 0.f;
    const __nv_bfloat16* yr = y0b + (size_t)r * ystride;
    for (int d = t; d < 1024; d += 128) {
        float yv = __bfloat162float(yr[d]);
        s0 += yv * cw[d];
        s1 += yv * cw[1024 + d];
        s2 += yv * cw[2048 + d];
    }
    __shared__ float sh[3][128];
    sh[0][t] = s0; sh[1][t] = s1; sh[2][t] = s2;
    __syncthreads();
    for (int off = 64; off > 0; off >>= 1) {
        if (t < off) {
            sh[0][t] += sh[0][t + off];
            sh[1][t] += sh[1][t + off];
            sh[2][t] += sh[2][t + off];
        }
        __syncthreads();
    }
    if (t < 3) clog[r * 3 + t] = sh[t][0] + cb[t];
}

// ---------------- finalize LSE ----------------
__global__ void lse_fin_k(const float* __restrict__ gsum,
                          const float* __restrict__ clog,
                          float* __restrict__ lse)
{
    int i = blockIdx.x * blockDim.x + threadIdx.x;
    if (i >= ROWS * 4) return;
    int r = i >> 2, c = i & 3;
    float s = gsum[i];
    if (c == 0)
        s += expf(clog[r * 3]) + expf(clog[r * 3 + 1]) + expf(clog[r * 3 + 2]);
    lse[i] = logf(s);
}

// ---------------- fixup clusters 0/1, scalar (VOCAB odd) ----------------
__global__ void fixup_k(float* __restrict__ out,
                        const float* __restrict__ clog,
                        const float* __restrict__ lse)
{
    int r = blockIdx.y;
    float l0 = lse[r * 4 + 0];
    float adj0 = -l0;
    float adj1 = clog[r * 3 + 0] - l0 - lse[r * 4 + 1];
    float* p = out + (size_t)r * VOCAB;
    int base = blockIdx.x * 10000;
    for (int col = base + threadIdx.x; col < base + 10000; col += blockDim.x) {
        float adj = (col < 20000) ? adj0 : adj1;
        p[col] += adj;
    }
}

// ---------------- loss ----------------
__global__ void loss_k(const float* __restrict__ out,
                       const int* __restrict__ target,
                       float* __restrict__ dst)
{
    int t = threadIdx.x;
    float v = out[(size_t)t * VOCAB + target[t]];
    __shared__ float sh[512];
    sh[t] = v;
    __syncthreads();
    for (int off = 256; off > 0; off >>= 1) {
        if (t < off) sh[t] += sh[t + off];
        __syncthreads();
    }
    if (t == 0) *dst = -sh[0] / 512.0f;
}

// ---------------- launcher ----------------
extern "C" void kernel_launch(void* const* d_in, const int* in_sizes, int n_in,
                              void* d_out, int out_size)
{
    const float *hidden = 0, *cw = 0, *cb = 0;
    const float *proj0 = 0, *proj1 = 0, *proj2 = 0, *proj3 = 0;
    const float *W0 = 0, *W1 = 0, *W2 = 0, *W3 = 0;
    const float *b0 = 0, *b1 = 0, *b2 = 0, *b3 = 0;
    const int *target = 0;

    for (int i = 0; i < n_in; i++) {
        const void* p = d_in[i];
        switch (in_sizes[i]) {
            case 524288:   hidden = (const float*)p; break;
            case 512:      target = (const int*)p;   break;
            case 3072:     cw = (const float*)p;     break;
            case 3:        cb = (const float*)p;     break;
            case 1048576:  proj0 = (const float*)p;  break;
            case 20480000: W0 = (const float*)p;     break;
            case 262144:   proj1 = (const float*)p;  break;
            case 5120000:  W1 = (const float*)p;     break;
            case 65536:    proj2 = (const float*)p;  break;
            case 10240000: W2 = (const float*)p;     break;
            case 160000:   b2 = (const float*)p;     break;
            case 16384:    proj3 = (const float*)p;  break;
            case 1083760:  W3 = (const float*)p;     break;
            case 67735:    b3 = (const float*)p;     break;
            case 20000:    if (!b0) b0 = (const float*)p; else b1 = (const float*)p; break;
            default: break;
        }
    }
    float* out = (float*)d_out;

    __nv_bfloat16* bf = nullptr;
    cudaGetSymbolAddress((void**)&bf, g_bf);
    float* f32s = nullptr;
    cudaGetSymbolAddress((void**)&f32s, g_f32);
    float* gsum = nullptr;
    cudaGetSymbolAddress((void**)&gsum, g_sum);
    float* clog = f32s;
    float* lse  = f32s + ROWS * 3;

    cudaFuncSetAttribute(proj_gemm_k, cudaFuncAttributeMaxDynamicSharedMemorySize, SM_GEMM);
    cudaFuncSetAttribute(logits_k, cudaFuncAttributeMaxDynamicSharedMemorySize, SM_LOG2);

    conv_all_k<<<2368, 256>>>(W0, W1, W2, W3, proj0, proj1, proj2, proj3, hidden);

    proj_gemm_k<<<dim3(6, 4), 256, SM_GEMM>>>(bf + B_H, 1024, bf + B_P0, 1360, 1024,
        bf + B_Y, 1360);

    cluster_logits_k<<<ROWS, 128>>>(bf + B_Y, 1360, cw, cb, clog);

    // pass 1: c0/c1 raw store + sums; c2/c3 grouped sums only
    logits_k<<<dim3(492, 4), 256, SM_LOG>>>(0, out, b0, b1, b2, b3, gsum,
                                            nullptr, nullptr);
    lse_fin_k<<<2, 1024>>>(gsum, clog, lse);

    // pass 2: grouped recompute + adjusted store (c2/c3)
    logits_k<<<dim3(178, 4), 256, SM_LOG2>>>(1, out, b0, b1, b2, b3, nullptr,
                                             clog, lse);
    fixup_k<<<dim3(4, ROWS), 256>>>(out, clog, lse);

    long total = (long)ROWS * VOCAB;
    if ((long)out_size > total)
        loss_k<<<1, ROWS>>>(out, target, out + total);
}